// round 1
// baseline (speedup 1.0000x reference)
#include <cuda_runtime.h>
#include <math.h>

#define BATCH 256
#define MEAS  32
#define SPM   16
#define TBEAT 512          // MEAS * SPM
#define INDIM 512
#define HDIM  1024
#define ODIM  128
#define G4    4096         // 4 * HDIM
#define KBEAT 1152         // HDIM + ODIM

// ---------------- scratch (__device__ globals; no allocation allowed) -------
__device__ float g_mWihP[G4 * INDIM];               //  8 MB  permuted measure Wih
__device__ float g_mWhhP[G4 * HDIM];                // 16 MB  permuted measure Whh
__device__ float g_WbP[G4 * KBEAT];                 // 19 MB  permuted [bWhh | bWih_O]
__device__ float g_bWihLatP[G4 * HDIM];             // 16 MB  permuted bWih lat-part
__device__ float g_mbP[G4];
__device__ float g_bbP[G4];
__device__ float g_xg[BATCH * MEAS * G4];           // 134 MB measure gate pre-acts
__device__ float g_lat[BATCH * MEAS * HDIM];        //  33 MB tanh(h) measure trace
__device__ float g_latproj[BATCH * MEAS * G4];      // 134 MB lat @ bWih_lat^T + bb
__device__ float g_h0[BATCH * HDIM];
__device__ float g_h1[BATCH * HDIM];
__device__ float g_c[BATCH * HDIM];
__device__ float g_hall[BATCH * TBEAT * HDIM];      // 537 MB tanh(h) beat trace

__device__ __forceinline__ float sigf(float x) { return 1.0f / (1.0f + expf(-x)); }

// ---------------- prep kernels: gate-interleaved weight permutes ------------
// dst row n = unit j * 4 + gate g  <-  src row g*HDIM + j   (PyTorch i,f,g,o)
__global__ void permute_rows_k(const float* __restrict__ src, float* __restrict__ dst,
                               int K, int srcStride) {
    int n = blockIdx.x;
    int j = n >> 2, g = n & 3;
    const float* s = src + (size_t)(g * HDIM + j) * srcStride;
    float* d = dst + (size_t)n * K;
    for (int k = threadIdx.x; k < K; k += blockDim.x) d[k] = s[k];
}

// combined beat recurrent weights: cols [0,1024) from bWhh, [1024,1152) from bWih[:,H:]
__global__ void build_wb_k(const float* __restrict__ bWhh, const float* __restrict__ bWih,
                           float* __restrict__ dst) {
    int n = blockIdx.x;
    int j = n >> 2, g = n & 3;
    const float* s1 = bWhh + (size_t)(g * HDIM + j) * HDIM;
    const float* s2 = bWih + (size_t)(g * HDIM + j) * KBEAT + HDIM;
    float* d = dst + (size_t)n * KBEAT;
    for (int k = threadIdx.x; k < HDIM; k += blockDim.x) d[k] = s1[k];
    for (int k = threadIdx.x; k < ODIM; k += blockDim.x) d[HDIM + k] = s2[k];
}

__global__ void permute_bias_k(const float* __restrict__ mb, const float* __restrict__ bb) {
    int n = blockIdx.x * blockDim.x + threadIdx.x;
    if (n < G4) {
        int j = n >> 2, g = n & 3;
        g_mbP[n] = mb[g * HDIM + j];
        g_bbP[n] = bb[g * HDIM + j];
    }
}

__global__ void zero_hc_k() {
    int i = blockIdx.x * blockDim.x + threadIdx.x;
    if (i < BATCH * HDIM) { g_h0[i] = 0.f; g_c[i] = 0.f; }
}

// ---------------- generic tiled GEMM: C[M,N] = A[M,K] @ W[N,K]^T + bias[N] ---
// 64x64 tile, 256 threads, 4x4 micro-tile. M,N multiples of 64, K of 16.
__global__ void __launch_bounds__(256) gemm_bias_k(
    const float* __restrict__ A, const float* __restrict__ W,
    const float* __restrict__ bias, float* __restrict__ C, int N, int K) {
    __shared__ float As[16][68];
    __shared__ float Bs[16][68];
    int tid = threadIdx.x;
    int row0 = blockIdx.y * 64, col0 = blockIdx.x * 64;
    int lr = tid >> 2;
    int lk = (tid & 3) << 2;
    const float* Ag = A + (size_t)(row0 + lr) * K + lk;
    const float* Wg = W + (size_t)(col0 + lr) * K + lk;
    int ty = tid >> 4, tx = tid & 15;
    float acc[4][4] = {};
    for (int kt = 0; kt < K; kt += 16) {
        float4 av = *(const float4*)(Ag + kt);
        float4 wv = *(const float4*)(Wg + kt);
        As[lk + 0][lr] = av.x; As[lk + 1][lr] = av.y;
        As[lk + 2][lr] = av.z; As[lk + 3][lr] = av.w;
        Bs[lk + 0][lr] = wv.x; Bs[lk + 1][lr] = wv.y;
        Bs[lk + 2][lr] = wv.z; Bs[lk + 3][lr] = wv.w;
        __syncthreads();
#pragma unroll
        for (int kk = 0; kk < 16; kk++) {
            float4 a4 = *(const float4*)&As[kk][ty * 4];
            float4 b4 = *(const float4*)&Bs[kk][tx * 4];
            float ar[4] = {a4.x, a4.y, a4.z, a4.w};
            float br[4] = {b4.x, b4.y, b4.z, b4.w};
#pragma unroll
            for (int i = 0; i < 4; i++)
#pragma unroll
                for (int jj = 0; jj < 4; jj++)
                    acc[i][jj] += ar[i] * br[jj];
        }
        __syncthreads();
    }
    float4 bv = *(const float4*)(bias + col0 + tx * 4);
#pragma unroll
    for (int i = 0; i < 4; i++) {
        float4 o;
        o.x = acc[i][0] + bv.x; o.y = acc[i][1] + bv.y;
        o.z = acc[i][2] + bv.z; o.w = acc[i][3] + bv.w;
        *(float4*)(C + (size_t)(row0 + ty * 4 + i) * N + col0 + tx * 4) = o;
    }
}

// ---------------- fused LSTM step: GEMM + gate nonlinearity + state update --
// Computes gates[r, j*4+g] = add[r, j*4+g] + sum_k A[r,k] * Wp[j*4+g, k]
// where A = h_in (k<HDIM) concatenated with extra (k>=HDIM, beat only).
// Then c' = sig(f)c + sig(i)tanh(g); h' = sig(o)tanh(c'); tanh_out = tanh(h').
template <int KDIM>
__global__ void __launch_bounds__(256) lstm_step_k(
    const float* __restrict__ h_in, const float* __restrict__ extra,
    const float* __restrict__ Wp, const float* __restrict__ add_base,
    float* __restrict__ h_out, float* __restrict__ c_state,
    float* __restrict__ tanh_out, int tanh_stride) {
    __shared__ float As[16][68];
    __shared__ float Bs[16][68];
    int tid = threadIdx.x;
    int row0 = blockIdx.y * 64, col0 = blockIdx.x * 64;
    int lr = tid >> 2;
    int lk = (tid & 3) << 2;
    int r_load = row0 + lr;
    const float* Wg = Wp + (size_t)(col0 + lr) * KDIM + lk;
    int ty = tid >> 4, tx = tid & 15;
    float acc[4][4] = {};
#pragma unroll 1
    for (int kt = 0; kt < KDIM; kt += 16) {
        int kg = kt + lk;
        float4 av;
        if (KDIM > HDIM && kg >= HDIM)
            av = *(const float4*)(extra + (size_t)r_load * (TBEAT * ODIM) + (kg - HDIM));
        else
            av = *(const float4*)(h_in + (size_t)r_load * HDIM + kg);
        float4 wv = *(const float4*)(Wg + kt);
        As[lk + 0][lr] = av.x; As[lk + 1][lr] = av.y;
        As[lk + 2][lr] = av.z; As[lk + 3][lr] = av.w;
        Bs[lk + 0][lr] = wv.x; Bs[lk + 1][lr] = wv.y;
        Bs[lk + 2][lr] = wv.z; Bs[lk + 3][lr] = wv.w;
        __syncthreads();
#pragma unroll
        for (int kk = 0; kk < 16; kk++) {
            float4 a4 = *(const float4*)&As[kk][ty * 4];
            float4 b4 = *(const float4*)&Bs[kk][tx * 4];
            float ar[4] = {a4.x, a4.y, a4.z, a4.w};
            float br[4] = {b4.x, b4.y, b4.z, b4.w};
#pragma unroll
            for (int i = 0; i < 4; i++)
#pragma unroll
                for (int jj = 0; jj < 4; jj++)
                    acc[i][jj] += ar[i] * br[jj];
        }
        __syncthreads();
    }
    int j = (col0 >> 2) + tx;  // hidden unit index
#pragma unroll
    for (int i = 0; i < 4; i++) {
        int r = row0 + ty * 4 + i;
        float4 ad = *(const float4*)(add_base + (size_t)r * (MEAS * G4) + (size_t)j * 4);
        float gi = acc[i][0] + ad.x;
        float gf = acc[i][1] + ad.y;
        float gg = acc[i][2] + ad.z;
        float go = acc[i][3] + ad.w;
        int ci = r * HDIM + j;
        float cc = sigf(gf) * c_state[ci] + sigf(gi) * tanhf(gg);
        c_state[ci] = cc;
        float hh = sigf(go) * tanhf(cc);
        h_out[ci] = hh;
        tanh_out[(size_t)r * tanh_stride + j] = tanhf(hh);
    }
}

// ---------------------------------------------------------------------------
extern "C" void kernel_launch(void* const* d_in, const int* in_sizes, int n_in,
                              void* d_out, int out_size) {
    const float* latent = (const float*)d_in[0];
    const float* inputs = (const float*)d_in[1];
    const float* mWih   = (const float*)d_in[2];
    const float* mWhh   = (const float*)d_in[3];
    const float* mb     = (const float*)d_in[4];
    const float* bWih   = (const float*)d_in[5];
    const float* bWhh   = (const float*)d_in[6];
    const float* bb     = (const float*)d_in[7];
    const float* linW   = (const float*)d_in[8];
    const float* linb   = (const float*)d_in[9];
    float* out = (float*)d_out;

    float *p_mWihP, *p_mWhhP, *p_WbP, *p_bWihLatP, *p_mbP, *p_bbP;
    float *p_xg, *p_lat, *p_latproj, *p_h0, *p_h1, *p_c, *p_hall;
    cudaGetSymbolAddress((void**)&p_mWihP, g_mWihP);
    cudaGetSymbolAddress((void**)&p_mWhhP, g_mWhhP);
    cudaGetSymbolAddress((void**)&p_WbP, g_WbP);
    cudaGetSymbolAddress((void**)&p_bWihLatP, g_bWihLatP);
    cudaGetSymbolAddress((void**)&p_mbP, g_mbP);
    cudaGetSymbolAddress((void**)&p_bbP, g_bbP);
    cudaGetSymbolAddress((void**)&p_xg, g_xg);
    cudaGetSymbolAddress((void**)&p_lat, g_lat);
    cudaGetSymbolAddress((void**)&p_latproj, g_latproj);
    cudaGetSymbolAddress((void**)&p_h0, g_h0);
    cudaGetSymbolAddress((void**)&p_h1, g_h1);
    cudaGetSymbolAddress((void**)&p_c, g_c);
    cudaGetSymbolAddress((void**)&p_hall, g_hall);

    // --- prep: permute weights into gate-interleaved layout ---
    permute_bias_k<<<16, 256>>>(mb, bb);
    permute_rows_k<<<G4, 256>>>(mWih, p_mWihP, INDIM, INDIM);
    permute_rows_k<<<G4, 256>>>(mWhh, p_mWhhP, HDIM, HDIM);
    permute_rows_k<<<G4, 256>>>(bWih, p_bWihLatP, HDIM, KBEAT);
    build_wb_k<<<G4, 256>>>(bWhh, bWih, p_WbP);

    // --- measure LSTM input projection: xg = latent @ mWihP^T + mbP ---
    gemm_bias_k<<<dim3(G4 / 64, (BATCH * MEAS) / 64), 256>>>(
        latent, p_mWihP, p_mbP, p_xg, G4, INDIM);

    // --- measure LSTM recurrence (32 steps) ---
    zero_hc_k<<<(BATCH * HDIM) / 256, 256>>>();
    for (int t = 0; t < MEAS; t++) {
        const float* hi = (t & 1) ? p_h1 : p_h0;
        float* ho = (t & 1) ? p_h0 : p_h1;
        lstm_step_k<HDIM><<<dim3(G4 / 64, BATCH / 64), 256>>>(
            hi, nullptr, p_mWhhP, p_xg + t * G4, ho, p_c,
            p_lat + t * HDIM, MEAS * HDIM);
    }

    // --- beat latent projection (once per measure, not per beat step) ---
    gemm_bias_k<<<dim3(G4 / 64, (BATCH * MEAS) / 64), 256>>>(
        p_lat, p_bWihLatP, p_bbP, p_latproj, G4, HDIM);

    // --- beat LSTM recurrence (512 steps); inputs proj fused into GEMM K dim ---
    zero_hc_k<<<(BATCH * HDIM) / 256, 256>>>();
    for (int t = 0; t < TBEAT; t++) {
        const float* hi = (t & 1) ? p_h1 : p_h0;
        float* ho = (t & 1) ? p_h0 : p_h1;
        lstm_step_k<KBEAT><<<dim3(G4 / 64, BATCH / 64), 256>>>(
            hi, inputs + t * ODIM, p_WbP, p_latproj + (t >> 4) * G4, ho, p_c,
            p_hall + t * HDIM, TBEAT * HDIM);
    }

    // --- output head: out = tanh(h_all) @ linW^T + linb ---
    gemm_bias_k<<<dim3(ODIM / 64, (BATCH * TBEAT) / 64), 256>>>(
        p_hall, linW, linb, out, ODIM, HDIM);
}

// round 2
// speedup vs baseline: 1.6285x; 1.6285x over previous
#include <cuda_runtime.h>
#include <math.h>
#include <stdint.h>

#define BATCH 256
#define MEAS  32
#define SPM   16
#define TBEAT 512          // MEAS * SPM
#define INDIM 512
#define HDIM  1024
#define ODIM  128
#define G4    4096         // 4 * HDIM
#define KBEAT 1152         // HDIM + ODIM

#define BM   64            // rows per block
#define BNC  128           // gate-cols per block
#define BU   32            // units per block (LSTM mode: BNC = 4 gates * BU)
#define BK   16
#define APAD 20
#define BPAD 20

// ---------------- scratch (__device__ globals; no allocation allowed) -------
__device__ float g_WbP[G4 * KBEAT];                 // 19 MB  [bWhh | bWih_O]
__device__ float g_xg[BATCH * MEAS * G4];           // 134 MB measure gate pre-acts
__device__ float g_lat[BATCH * MEAS * HDIM];        //  33 MB tanh(h) measure trace
__device__ float g_latproj[BATCH * MEAS * G4];      // 134 MB lat @ bWih_lat^T + bb
__device__ float g_h0[BATCH * HDIM];
__device__ float g_h1[BATCH * HDIM];
__device__ float g_c[BATCH * HDIM];
__device__ float g_hall[BATCH * TBEAT * HDIM];      // 537 MB tanh(h) beat trace

__device__ __forceinline__ float sigf(float x) { return 1.0f / (1.0f + expf(-x)); }

__device__ __forceinline__ uint32_t f2tf32(float x) {
    uint32_t r;
    asm("cvt.rna.tf32.f32 %0, %1;" : "=r"(r) : "f"(x));
    return r;
}

__device__ __forceinline__ void mma_tf32(float* c, uint32_t a0, uint32_t a1,
                                         uint32_t a2, uint32_t a3,
                                         uint32_t b0, uint32_t b1) {
    asm volatile(
        "mma.sync.aligned.m16n8k8.row.col.f32.tf32.tf32.f32 "
        "{%0,%1,%2,%3}, {%4,%5,%6,%7}, {%8,%9}, {%0,%1,%2,%3};"
        : "+f"(c[0]), "+f"(c[1]), "+f"(c[2]), "+f"(c[3])
        : "r"(a0), "r"(a1), "r"(a2), "r"(a3), "r"(b0), "r"(b1));
}

// in-smem k permutation within a 16-wide tile: pairs (k, k+4) adjacent
__device__ __forceinline__ int KS(int k) {
    return ((k & 3) << 1) + ((k >> 2) & 1) + ((k >> 3) << 3);
}

// ---------------- prep kernels ----------------------------------------------
// combined beat recurrent weights: cols [0,1024) from bWhh, [1024,1152) bWih[:,H:]
__global__ void build_wb_k(const float* __restrict__ bWhh, const float* __restrict__ bWih,
                           float* __restrict__ dst) {
    int n = blockIdx.x;
    const float* s1 = bWhh + (size_t)n * HDIM;
    const float* s2 = bWih + (size_t)n * KBEAT + HDIM;
    float* d = dst + (size_t)n * KBEAT;
    for (int k = threadIdx.x; k < HDIM; k += blockDim.x) d[k] = s1[k];
    for (int k = threadIdx.x; k < ODIM; k += blockDim.x) d[HDIM + k] = s2[k];
}

__global__ void zero_hc_k() {
    int i = blockIdx.x * blockDim.x + threadIdx.x;
    if (i < BATCH * HDIM) { g_h0[i] = 0.f; g_c[i] = 0.f; }
}

// ---------------- tf32 tensor GEMM, optional fused LSTM epilogue ------------
// C[M, N] = A[M, K(lda)] @ W[N(brow-mapped), K(ldw)]^T   (+ bias / LSTM update)
// LSTM mode: N-block covers BU units x 4 gates at rows g*HDIM + u (PyTorch order).
// HAS_EXTRA: for k >= HDIM, A columns come from `extra` (beat inputs).
template<bool LSTM, bool HAS_EXTRA>
__global__ void __launch_bounds__(256) tgemm_k(
    const float* __restrict__ A, int lda,
    const float* __restrict__ extra,
    const float* __restrict__ W, int ldw, int K,
    const float* __restrict__ bias_or_add, int addStride,
    float* __restrict__ out_or_h, int ldc,
    float* __restrict__ c_state,
    float* __restrict__ tanh_out, int tanh_stride)
{
    __shared__ uint32_t As[2][BM * APAD];
    __shared__ uint32_t Bs[2][BNC * BPAD];

    const int tid  = threadIdx.x;
    const int wid  = tid >> 5;
    const int lane = tid & 31;
    const int wm   = wid >> 1;     // 0..3 : warp row group (16 rows each)
    const int wu   = wid & 1;      // 0..1 : warp col group
    const int q    = lane & 3;
    const int rg   = lane >> 2;    // 0..7

    const int mblk = blockIdx.y * BM;
    const int nblk = blockIdx.x;

    // global-load assignments (one A float4, two B float4 per thread per tile)
    const int a_row = tid >> 2;
    const int a_k4  = (tid & 3) << 2;
    const int b_cn  = tid >> 2;
    const int b_k4  = (tid & 3) << 2;

    int brow0, brow1;
    if (LSTM) {
        brow0 = (b_cn >> 5) * HDIM + nblk * BU + (b_cn & 31);
        int c2 = b_cn + 64;
        brow1 = (c2 >> 5) * HDIM + nblk * BU + (c2 & 31);
    } else {
        brow0 = nblk * BNC + b_cn;
        brow1 = nblk * BNC + b_cn + 64;
    }
    const float* Wp0 = W + (size_t)brow0 * ldw + b_k4;
    const float* Wp1 = W + (size_t)brow1 * ldw + b_k4;
    const float* Ap0 = A + (size_t)(mblk + a_row) * lda + a_k4;
    const float* Ep0 = HAS_EXTRA ?
        (extra + (size_t)(mblk + a_row) * (TBEAT * ODIM) + a_k4) : (const float*)0;

    float acc[8][4];
#pragma unroll
    for (int i = 0; i < 8; i++)
#pragma unroll
        for (int j = 0; j < 4; j++) acc[i][j] = 0.f;

    float4 av, bv0, bv1;
    av  = *(const float4*)Ap0;       // tile 0 is always below HDIM
    bv0 = *(const float4*)Wp0;
    bv1 = *(const float4*)Wp1;

    // store tile 0 into buffer 0
    {
        uint32_t* as = As[0];
        uint32_t* bs = Bs[0];
        as[a_row * APAD + a_k4 + 0] = f2tf32(av.x);
        as[a_row * APAD + a_k4 + 1] = f2tf32(av.y);
        as[a_row * APAD + a_k4 + 2] = f2tf32(av.z);
        as[a_row * APAD + a_k4 + 3] = f2tf32(av.w);
        bs[b_cn * BPAD + KS(b_k4 + 0)] = f2tf32(bv0.x);
        bs[b_cn * BPAD + KS(b_k4 + 1)] = f2tf32(bv0.y);
        bs[b_cn * BPAD + KS(b_k4 + 2)] = f2tf32(bv0.z);
        bs[b_cn * BPAD + KS(b_k4 + 3)] = f2tf32(bv0.w);
        bs[(b_cn + 64) * BPAD + KS(b_k4 + 0)] = f2tf32(bv1.x);
        bs[(b_cn + 64) * BPAD + KS(b_k4 + 1)] = f2tf32(bv1.y);
        bs[(b_cn + 64) * BPAD + KS(b_k4 + 2)] = f2tf32(bv1.z);
        bs[(b_cn + 64) * BPAD + KS(b_k4 + 3)] = f2tf32(bv1.w);
    }
    __syncthreads();

    const int nk = K / BK;
    for (int it = 0; it < nk; ++it) {
        const int cur = it & 1;
        if (it + 1 < nk) {
            const int kt = (it + 1) * BK;
            if (HAS_EXTRA && kt >= HDIM)
                av = *(const float4*)(Ep0 + (kt - HDIM));
            else
                av = *(const float4*)(Ap0 + kt);
            bv0 = *(const float4*)(Wp0 + kt);
            bv1 = *(const float4*)(Wp1 + kt);
        }
        const uint32_t* as = As[cur];
        const uint32_t* bs = Bs[cur];
#pragma unroll
        for (int G = 0; G < 2; ++G) {
            uint32_t a0 = as[(wm * 16 + rg) * APAD + G * 8 + q];
            uint32_t a1 = as[(wm * 16 + rg + 8) * APAD + G * 8 + q];
            uint32_t a2 = as[(wm * 16 + rg) * APAD + G * 8 + q + 4];
            uint32_t a3 = as[(wm * 16 + rg + 8) * APAD + G * 8 + q + 4];
#pragma unroll
            for (int nt = 0; nt < 8; ++nt) {
                const int cn0 = LSTM ? ((nt >> 1) * BU + wu * 16 + (nt & 1) * 8)
                                     : (wu * 64 + nt * 8);
                const uint2 bb = *(const uint2*)&bs[(cn0 + rg) * BPAD + 2 * q + 8 * G];
                mma_tf32(acc[nt], a0, a1, a2, a3, bb.x, bb.y);
            }
        }
        if (it + 1 < nk) {
            uint32_t* asn = As[cur ^ 1];
            uint32_t* bsn = Bs[cur ^ 1];
            asn[a_row * APAD + a_k4 + 0] = f2tf32(av.x);
            asn[a_row * APAD + a_k4 + 1] = f2tf32(av.y);
            asn[a_row * APAD + a_k4 + 2] = f2tf32(av.z);
            asn[a_row * APAD + a_k4 + 3] = f2tf32(av.w);
            bsn[b_cn * BPAD + KS(b_k4 + 0)] = f2tf32(bv0.x);
            bsn[b_cn * BPAD + KS(b_k4 + 1)] = f2tf32(bv0.y);
            bsn[b_cn * BPAD + KS(b_k4 + 2)] = f2tf32(bv0.z);
            bsn[b_cn * BPAD + KS(b_k4 + 3)] = f2tf32(bv0.w);
            bsn[(b_cn + 64) * BPAD + KS(b_k4 + 0)] = f2tf32(bv1.x);
            bsn[(b_cn + 64) * BPAD + KS(b_k4 + 1)] = f2tf32(bv1.y);
            bsn[(b_cn + 64) * BPAD + KS(b_k4 + 2)] = f2tf32(bv1.z);
            bsn[(b_cn + 64) * BPAD + KS(b_k4 + 3)] = f2tf32(bv1.w);
        }
        __syncthreads();
    }

    // ---------------- epilogue ----------------
    const int r0 = mblk + wm * 16 + rg;
    if (LSTM) {
#pragma unroll
        for (int ut = 0; ut < 2; ++ut)
#pragma unroll
            for (int rsel = 0; rsel < 2; ++rsel)
#pragma unroll
                for (int ps = 0; ps < 2; ++ps) {
                    const int r = r0 + rsel * 8;
                    const int j = nblk * BU + wu * 16 + ut * 8 + 2 * q + ps;
                    const int ai = rsel * 2 + ps;
                    const float* ad = bias_or_add + (size_t)r * addStride + j;
                    float gi = acc[0 * 2 + ut][ai] + ad[0 * HDIM];
                    float gf = acc[1 * 2 + ut][ai] + ad[1 * HDIM];
                    float gg = acc[2 * 2 + ut][ai] + ad[2 * HDIM];
                    float go = acc[3 * 2 + ut][ai] + ad[3 * HDIM];
                    const int ci = r * HDIM + j;
                    float cc = sigf(gf) * c_state[ci] + sigf(gi) * tanhf(gg);
                    c_state[ci] = cc;
                    float hh = sigf(go) * tanhf(cc);
                    out_or_h[ci] = hh;
                    tanh_out[(size_t)r * tanh_stride + j] = tanhf(hh);
                }
    } else {
#pragma unroll
        for (int nt = 0; nt < 8; ++nt)
#pragma unroll
            for (int rsel = 0; rsel < 2; ++rsel) {
                const int r = r0 + rsel * 8;
                const int col = nblk * BNC + wu * 64 + nt * 8 + 2 * q;
                float2 o;
                o.x = acc[nt][rsel * 2 + 0] + bias_or_add[col];
                o.y = acc[nt][rsel * 2 + 1] + bias_or_add[col + 1];
                *(float2*)&out_or_h[(size_t)r * ldc + col] = o;
            }
    }
}

// ---------------------------------------------------------------------------
extern "C" void kernel_launch(void* const* d_in, const int* in_sizes, int n_in,
                              void* d_out, int out_size) {
    const float* latent = (const float*)d_in[0];
    const float* inputs = (const float*)d_in[1];
    const float* mWih   = (const float*)d_in[2];
    const float* mWhh   = (const float*)d_in[3];
    const float* mb     = (const float*)d_in[4];
    const float* bWih   = (const float*)d_in[5];
    const float* bWhh   = (const float*)d_in[6];
    const float* bb     = (const float*)d_in[7];
    const float* linW   = (const float*)d_in[8];
    const float* linb   = (const float*)d_in[9];
    float* out = (float*)d_out;

    float *p_WbP, *p_xg, *p_lat, *p_latproj, *p_h0, *p_h1, *p_c, *p_hall;
    cudaGetSymbolAddress((void**)&p_WbP, g_WbP);
    cudaGetSymbolAddress((void**)&p_xg, g_xg);
    cudaGetSymbolAddress((void**)&p_lat, g_lat);
    cudaGetSymbolAddress((void**)&p_latproj, g_latproj);
    cudaGetSymbolAddress((void**)&p_h0, g_h0);
    cudaGetSymbolAddress((void**)&p_h1, g_h1);
    cudaGetSymbolAddress((void**)&p_c, g_c);
    cudaGetSymbolAddress((void**)&p_hall, g_hall);

    // prep: concat beat recurrent weights
    build_wb_k<<<G4, 256>>>(bWhh, bWih, p_WbP);

    // measure input projection: xg = latent @ mWih^T + mb   [8192 x 4096]
    tgemm_k<false, false><<<dim3(G4 / BNC, (BATCH * MEAS) / BM), 256>>>(
        latent, INDIM, nullptr, mWih, INDIM, INDIM,
        mb, 0, p_xg, G4, nullptr, nullptr, 0);

    // measure LSTM (32 steps)
    zero_hc_k<<<(BATCH * HDIM) / 256, 256>>>();
    for (int t = 0; t < MEAS; t++) {
        const float* hi = (t & 1) ? p_h1 : p_h0;
        float* ho = (t & 1) ? p_h0 : p_h1;
        tgemm_k<true, false><<<dim3(HDIM / BU, BATCH / BM), 256>>>(
            hi, HDIM, nullptr, mWhh, HDIM, HDIM,
            p_xg + t * G4, MEAS * G4, ho, 0, p_c,
            p_lat + t * HDIM, MEAS * HDIM);
    }

    // beat latent projection: latproj = lat @ bWih[:, :H]^T + bb  [8192 x 4096]
    tgemm_k<false, false><<<dim3(G4 / BNC, (BATCH * MEAS) / BM), 256>>>(
        p_lat, HDIM, nullptr, bWih, KBEAT, HDIM,
        bb, 0, p_latproj, G4, nullptr, nullptr, 0);

    // beat LSTM (512 steps); inputs projection fused into GEMM K dim
    zero_hc_k<<<(BATCH * HDIM) / 256, 256>>>();
    for (int t = 0; t < TBEAT; t++) {
        const float* hi = (t & 1) ? p_h1 : p_h0;
        float* ho = (t & 1) ? p_h0 : p_h1;
        tgemm_k<true, true><<<dim3(HDIM / BU, BATCH / BM), 256>>>(
            hi, HDIM, inputs + t * ODIM, p_WbP, KBEAT, KBEAT,
            p_latproj + (t >> 4) * G4, MEAS * G4, ho, 0, p_c,
            p_hall + t * HDIM, TBEAT * HDIM);
    }

    // output head: out = tanh(h_all) @ linW^T + linb  [131072 x 128]
    tgemm_k<false, false><<<dim3(ODIM / BNC, (BATCH * TBEAT) / BM), 256>>>(
        p_hall, HDIM, nullptr, linW, HDIM, HDIM,
        linb, 0, out, ODIM, nullptr, nullptr, 0);
}

// round 3
// speedup vs baseline: 2.1065x; 1.2936x over previous
#include <cuda_runtime.h>
#include <math.h>
#include <stdint.h>

#define BATCH 256
#define MEAS  32
#define TBEAT 512
#define INDIM 512
#define HDIM  1024
#define ODIM  128
#define G4    4096
#define KBEAT 1152

#define BM    128          // rows per CTA
#define BNC   64           // gate-cols per CTA (LSTM: 16 units x 4 gates)
#define BK    16
#define APAD  20
#define BPAD  24
#define STAGES 3

// ---------------- scratch (__device__ globals) -------------------------------
__device__ float g_WbR[G4 * KBEAT];            // rounded+permuted [bWhh | bWih_O]
__device__ float g_mWihR[G4 * INDIM];
__device__ float g_mWhhR[G4 * HDIM];
__device__ float g_latWR[G4 * HDIM];           // bWih[:, :H]
__device__ float g_linWR[ODIM * HDIM];
__device__ float g_latentR[BATCH * MEAS * INDIM];
__device__ float g_inR[BATCH * TBEAT * ODIM];
__device__ float g_xg[BATCH * MEAS * G4];
__device__ float g_lat[BATCH * MEAS * HDIM];
__device__ float g_latproj[BATCH * MEAS * G4];
__device__ float g_h0[BATCH * HDIM];
__device__ float g_h1[BATCH * HDIM];
__device__ float g_c[BATCH * HDIM];
__device__ float g_hall[BATCH * TBEAT * HDIM];

__device__ __forceinline__ float sigf(float x) { return 1.0f / (1.0f + expf(-x)); }

__device__ __forceinline__ uint32_t f2tf32(float x) {
    uint32_t r;
    asm("cvt.rna.tf32.f32 %0, %1;" : "=r"(r) : "f"(x));
    return r;
}

__device__ __forceinline__ void mma_tf32(float* c, uint32_t a0, uint32_t a1,
                                         uint32_t a2, uint32_t a3,
                                         uint32_t b0, uint32_t b1) {
    asm volatile(
        "mma.sync.aligned.m16n8k8.row.col.f32.tf32.tf32.f32 "
        "{%0,%1,%2,%3}, {%4,%5,%6,%7}, {%8,%9}, {%0,%1,%2,%3};"
        : "+f"(c[0]), "+f"(c[1]), "+f"(c[2]), "+f"(c[3])
        : "r"(a0), "r"(a1), "r"(a2), "r"(a3), "r"(b0), "r"(b1));
}

// k permutation within 16: pairs (k, k+4) adjacent -> uint2 B-frag loads
__device__ __forceinline__ int KS(int k) {
    return ((k & 3) << 1) + ((k >> 2) & 1) + ((k >> 3) << 3);
}

__device__ __forceinline__ void cpa16(float* smem, const float* g) {
    uint32_t sa = (uint32_t)__cvta_generic_to_shared(smem);
    asm volatile("cp.async.cg.shared.global [%0], [%1], 16;" :: "r"(sa), "l"(g));
}

// ---------------- prep kernels ----------------------------------------------
__global__ void round_copy_k(const float* __restrict__ src, float* __restrict__ dst, int n) {
    int i = blockIdx.x * blockDim.x + threadIdx.x;
    if (i < n) dst[i] = __uint_as_float(f2tf32(src[i]));
}

// round to tf32 + KS-permute each aligned 16-block of a weight row
__global__ void wprep_k(const float* __restrict__ src, int srcStride,
                        float* __restrict__ dst, int K) {
    int n = blockIdx.x;
    const float* s = src + (size_t)n * srcStride;
    float* d = dst + (size_t)n * K;
    for (int k = threadIdx.x; k < K; k += blockDim.x)
        d[(k & ~15) + KS(k & 15)] = __uint_as_float(f2tf32(s[k]));
}

// combined beat weights: k<1024 from bWhh, k>=1024 from bWih (col index = k)
__global__ void wbprep_k(const float* __restrict__ bWhh, const float* __restrict__ bWih,
                         float* __restrict__ dst) {
    int n = blockIdx.x;
    float* d = dst + (size_t)n * KBEAT;
    for (int k = threadIdx.x; k < KBEAT; k += blockDim.x) {
        float v = (k < HDIM) ? bWhh[(size_t)n * HDIM + k]
                             : bWih[(size_t)n * KBEAT + k];
        d[(k & ~15) + KS(k & 15)] = __uint_as_float(f2tf32(v));
    }
}

__global__ void zero_hc_k() {
    int i = blockIdx.x * blockDim.x + threadIdx.x;
    if (i < BATCH * HDIM) { g_h0[i] = 0.f; g_c[i] = 0.f; }
}

// ---------------- tf32 tensor GEMM w/ cp.async pipeline + fused LSTM --------
// C[M,N] = A[M,K] @ W[N(row-mapped),K]^T ; W is pre-rounded + KS-permuted.
// LSTM: CTA covers 16 units x 4 gates; warp wn covers units wn*8..+7, all gates.
template<bool LSTM, bool HAS_EXTRA>
__global__ void __launch_bounds__(128) tgemm_k(
    const float* __restrict__ A, int lda,
    const float* __restrict__ extra,
    const float* __restrict__ W, int ldw, int K,
    const float* __restrict__ bias_or_add, int addStride,
    float* __restrict__ out_or_h, int ldc,
    float* __restrict__ c_state,
    float* __restrict__ tanh_out, long long tanh_stride)
{
    __shared__ float As[STAGES][BM * APAD];
    __shared__ float Bs[STAGES][BNC * BPAD];

    const int tid  = threadIdx.x;
    const int wid  = tid >> 5;
    const int lane = tid & 31;
    const int wm   = wid >> 1;          // 0..1 : 64-row group
    const int wn   = wid & 1;           // 0..1 : 32-col group
    const int q    = lane & 3;
    const int rg   = lane >> 2;
    const int mblk = blockIdx.y * BM;
    const int nblk = blockIdx.x;

    const int lrow = tid >> 2;          // 0..31
    const int lk4  = (tid & 3) << 2;    // 0,4,8,12

    // global src pointers for the loader
    const float* Ap[4];
    const float* Ep[4];
#pragma unroll
    for (int p = 0; p < 4; p++) {
        int r = mblk + lrow + 32 * p;
        Ap[p] = A + (size_t)r * lda + lk4;
        Ep[p] = HAS_EXTRA ? (extra + (size_t)r * (TBEAT * ODIM) + lk4) : (const float*)0;
    }
    const float* Bp[2];
#pragma unroll
    for (int p = 0; p < 2; p++) {
        int cn = lrow + 32 * p;
        int brow = LSTM ? ((cn >> 4) * HDIM + nblk * 16 + (cn & 15))
                        : (nblk * BNC + cn);
        Bp[p] = W + (size_t)brow * ldw + lk4;
    }
    // smem dst offsets
    int adst[4], bdst[2];
#pragma unroll
    for (int p = 0; p < 4; p++) adst[p] = (lrow + 32 * p) * APAD + lk4;
#pragma unroll
    for (int p = 0; p < 2; p++) bdst[p] = (lrow + 32 * p) * BPAD + lk4;

    const int nk = K / BK;

    auto issue = [&](int s, int it) {
        const int kt = it * BK;
#pragma unroll
        for (int p = 0; p < 4; p++) {
            const float* src = (HAS_EXTRA && kt >= HDIM) ? (Ep[p] + (kt - HDIM))
                                                         : (Ap[p] + kt);
            cpa16(&As[s][adst[p]], src);
        }
#pragma unroll
        for (int p = 0; p < 2; p++) cpa16(&Bs[s][bdst[p]], Bp[p] + kt);
    };

    // prologue: two stages in flight
    issue(0, 0);
    asm volatile("cp.async.commit_group;");
    issue(1, 1);
    asm volatile("cp.async.commit_group;");

    float acc[4][4][4];
#pragma unroll
    for (int a = 0; a < 4; a++)
#pragma unroll
        for (int b = 0; b < 4; b++)
#pragma unroll
            for (int cidx = 0; cidx < 4; cidx++) acc[a][b][cidx] = 0.f;

    int st = 0;            // compute stage
    int st2 = 2;           // issue stage
    for (int it = 0; it < nk; ++it) {
        asm volatile("cp.async.wait_group 1;");
        __syncthreads();
        const float* as = As[st];
        const float* bs = Bs[st];
#pragma unroll
        for (int G = 0; G < 2; ++G) {
            uint32_t a[4][4];
#pragma unroll
            for (int mt = 0; mt < 4; mt++) {
                const int r0 = (wm * 64 + mt * 16 + rg) * APAD + G * 8 + q;
                a[mt][0] = __float_as_uint(as[r0]);
                a[mt][1] = __float_as_uint(as[r0 + 8 * APAD]);
                a[mt][2] = __float_as_uint(as[r0 + 4]);
                a[mt][3] = __float_as_uint(as[r0 + 8 * APAD + 4]);
            }
#pragma unroll
            for (int nt = 0; nt < 4; nt++) {
                const int cn0 = LSTM ? (nt * 16 + wn * 8) : (wn * 32 + nt * 8);
                const uint2 bb = *(const uint2*)&bs[(cn0 + rg) * BPAD + 2 * q + 8 * G];
#pragma unroll
                for (int mt = 0; mt < 4; mt++)
                    mma_tf32(acc[mt][nt], a[mt][0], a[mt][1], a[mt][2], a[mt][3],
                             bb.x, bb.y);
            }
        }
        if (it + 2 < nk) issue(st2, it + 2);
        asm volatile("cp.async.commit_group;");
        st = (st == 2) ? 0 : st + 1;
        st2 = (st2 == 2) ? 0 : st2 + 1;
    }
    asm volatile("cp.async.wait_group 0;");

    // ---------------- epilogue ----------------
    if (LSTM) {
#pragma unroll
        for (int mt = 0; mt < 4; mt++)
#pragma unroll
            for (int rs = 0; rs < 2; rs++)
#pragma unroll
                for (int ps = 0; ps < 2; ps++) {
                    const int r = mblk + wm * 64 + mt * 16 + rg + rs * 8;
                    const int j = nblk * 16 + wn * 8 + 2 * q + ps;
                    const int ai = rs * 2 + ps;
                    const float* ad = bias_or_add + (size_t)r * addStride + j;
                    float gi = acc[mt][0][ai] + ad[0];
                    float gf = acc[mt][1][ai] + ad[HDIM];
                    float gg = acc[mt][2][ai] + ad[2 * HDIM];
                    float go = acc[mt][3][ai] + ad[3 * HDIM];
                    const int ci = r * HDIM + j;
                    float cc = sigf(gf) * c_state[ci] + sigf(gi) * tanhf(gg);
                    c_state[ci] = cc;
                    float hh = sigf(go) * tanhf(cc);
                    out_or_h[ci] = __uint_as_float(f2tf32(hh));
                    tanh_out[(size_t)r * tanh_stride + j] =
                        __uint_as_float(f2tf32(tanhf(hh)));
                }
    } else {
#pragma unroll
        for (int mt = 0; mt < 4; mt++)
#pragma unroll
            for (int nt = 0; nt < 4; nt++)
#pragma unroll
                for (int rs = 0; rs < 2; rs++) {
                    const int r = mblk + wm * 64 + mt * 16 + rg + rs * 8;
                    const int col = nblk * BNC + wn * 32 + nt * 8 + 2 * q;
                    float2 o;
                    o.x = acc[mt][nt][rs * 2 + 0] + bias_or_add[col];
                    o.y = acc[mt][nt][rs * 2 + 1] + bias_or_add[col + 1];
                    *(float2*)&out_or_h[(size_t)r * ldc + col] = o;
                }
    }
}

// ---------------------------------------------------------------------------
extern "C" void kernel_launch(void* const* d_in, const int* in_sizes, int n_in,
                              void* d_out, int out_size) {
    const float* latent = (const float*)d_in[0];
    const float* inputs = (const float*)d_in[1];
    const float* mWih   = (const float*)d_in[2];
    const float* mWhh   = (const float*)d_in[3];
    const float* mb     = (const float*)d_in[4];
    const float* bWih   = (const float*)d_in[5];
    const float* bWhh   = (const float*)d_in[6];
    const float* bb     = (const float*)d_in[7];
    const float* linW   = (const float*)d_in[8];
    const float* linb   = (const float*)d_in[9];
    float* out = (float*)d_out;

    float *p_WbR, *p_mWihR, *p_mWhhR, *p_latWR, *p_linWR, *p_latentR, *p_inR;
    float *p_xg, *p_lat, *p_latproj, *p_h0, *p_h1, *p_c, *p_hall;
    cudaGetSymbolAddress((void**)&p_WbR, g_WbR);
    cudaGetSymbolAddress((void**)&p_mWihR, g_mWihR);
    cudaGetSymbolAddress((void**)&p_mWhhR, g_mWhhR);
    cudaGetSymbolAddress((void**)&p_latWR, g_latWR);
    cudaGetSymbolAddress((void**)&p_linWR, g_linWR);
    cudaGetSymbolAddress((void**)&p_latentR, g_latentR);
    cudaGetSymbolAddress((void**)&p_inR, g_inR);
    cudaGetSymbolAddress((void**)&p_xg, g_xg);
    cudaGetSymbolAddress((void**)&p_lat, g_lat);
    cudaGetSymbolAddress((void**)&p_latproj, g_latproj);
    cudaGetSymbolAddress((void**)&p_h0, g_h0);
    cudaGetSymbolAddress((void**)&p_h1, g_h1);
    cudaGetSymbolAddress((void**)&p_c, g_c);
    cudaGetSymbolAddress((void**)&p_hall, g_hall);

    // --- prep: round activations; round + k-permute all MMA weights ---
    round_copy_k<<<(BATCH * MEAS * INDIM + 255) / 256, 256>>>(latent, p_latentR,
                                                              BATCH * MEAS * INDIM);
    round_copy_k<<<(BATCH * TBEAT * ODIM + 255) / 256, 256>>>(inputs, p_inR,
                                                              BATCH * TBEAT * ODIM);
    wprep_k<<<G4, 256>>>(mWih, INDIM, p_mWihR, INDIM);
    wprep_k<<<G4, 256>>>(mWhh, HDIM, p_mWhhR, HDIM);
    wprep_k<<<G4, 256>>>(bWih, KBEAT, p_latWR, HDIM);
    wprep_k<<<ODIM, 256>>>(linW, HDIM, p_linWR, HDIM);
    wbprep_k<<<G4, 256>>>(bWhh, bWih, p_WbR);

    // --- measure input projection: xg = latent @ mWih^T + mb ---
    tgemm_k<false, false><<<dim3(G4 / BNC, (BATCH * MEAS) / BM), 128>>>(
        p_latentR, INDIM, nullptr, p_mWihR, INDIM, INDIM,
        mb, 0, p_xg, G4, nullptr, nullptr, 0);

    // --- measure LSTM (32 steps) ---
    zero_hc_k<<<(BATCH * HDIM) / 256, 256>>>();
    for (int t = 0; t < MEAS; t++) {
        const float* hi = (t & 1) ? p_h1 : p_h0;
        float* ho = (t & 1) ? p_h0 : p_h1;
        tgemm_k<true, false><<<dim3(HDIM / 16, BATCH / BM), 128>>>(
            hi, HDIM, nullptr, p_mWhhR, HDIM, HDIM,
            p_xg + t * G4, MEAS * G4, ho, 0, p_c,
            p_lat + t * HDIM, (long long)MEAS * HDIM);
    }

    // --- beat latent projection: latproj = lat @ bWih[:, :H]^T + bb ---
    tgemm_k<false, false><<<dim3(G4 / BNC, (BATCH * MEAS) / BM), 128>>>(
        p_lat, HDIM, nullptr, p_latWR, HDIM, HDIM,
        bb, 0, p_latproj, G4, nullptr, nullptr, 0);

    // --- beat LSTM (512 steps); inputs proj fused into GEMM K dim ---
    zero_hc_k<<<(BATCH * HDIM) / 256, 256>>>();
    for (int t = 0; t < TBEAT; t++) {
        const float* hi = (t & 1) ? p_h1 : p_h0;
        float* ho = (t & 1) ? p_h0 : p_h1;
        tgemm_k<true, true><<<dim3(HDIM / 16, BATCH / BM), 128>>>(
            hi, HDIM, p_inR + t * ODIM, p_WbR, KBEAT, KBEAT,
            p_latproj + (t >> 4) * G4, MEAS * G4, ho, 0, p_c,
            p_hall + t * HDIM, (long long)TBEAT * HDIM);
    }

    // --- output head: out = tanh(h_all) @ linW^T + linb ---
    tgemm_k<false, false><<<dim3(ODIM / BNC, (BATCH * TBEAT) / BM), 128>>>(
        p_hall, HDIM, nullptr, p_linWR, HDIM, HDIM,
        linb, 0, out, ODIM, nullptr, nullptr, 0);
}

// round 4
// speedup vs baseline: 2.9796x; 1.4145x over previous
#include <cuda_runtime.h>
#include <math.h>
#include <stdint.h>

#define BATCH 256
#define MEAS  32
#define TBEAT 512
#define INDIM 512
#define HDIM  1024
#define ODIM  128
#define G4    4096
#define KBEAT 1152

#define BM    128          // rows per CTA
#define BNC   64           // gate-cols per CTA (LSTM: 16 units x 4 gates)
#define BK    32
#define APAD  36           // BK + 4  (LDS.32 conflict-free: 36 mod 32 = 4)
#define BPAD  40           // BK + 8  (LDS.64 conflict-free: 40 mod 32 = 8)
#define STAGES 3
#define SMEM_FLOATS (STAGES * (BM * APAD + BNC * BPAD))
#define SMEM_BYTES  (SMEM_FLOATS * 4)

// ---------------- scratch (__device__ globals) -------------------------------
__device__ float g_WbR[G4 * KBEAT];            // rounded+permuted [bWhh | bWih_O]
__device__ float g_mWihR[G4 * INDIM];
__device__ float g_mWhhR[G4 * HDIM];
__device__ float g_latWR[G4 * HDIM];           // bWih[:, :H]
__device__ float g_linWR[ODIM * HDIM];
__device__ float g_latentR[BATCH * MEAS * INDIM];
__device__ float g_inR[BATCH * TBEAT * ODIM];
__device__ float g_xg[BATCH * MEAS * G4];
__device__ float g_lat[BATCH * MEAS * HDIM];
__device__ float g_latproj[BATCH * MEAS * G4];
__device__ float g_h0[BATCH * HDIM];
__device__ float g_h1[BATCH * HDIM];
__device__ float g_c[BATCH * HDIM];
__device__ float g_hall[BATCH * TBEAT * HDIM];

__device__ __forceinline__ float sigf(float x) { return 1.0f / (1.0f + expf(-x)); }

__device__ __forceinline__ uint32_t f2tf32(float x) {
    uint32_t r;
    asm("cvt.rna.tf32.f32 %0, %1;" : "=r"(r) : "f"(x));
    return r;
}

__device__ __forceinline__ void mma_tf32(float* c, uint32_t a0, uint32_t a1,
                                         uint32_t a2, uint32_t a3,
                                         uint32_t b0, uint32_t b1) {
    asm volatile(
        "mma.sync.aligned.m16n8k8.row.col.f32.tf32.tf32.f32 "
        "{%0,%1,%2,%3}, {%4,%5,%6,%7}, {%8,%9}, {%0,%1,%2,%3};"
        : "+f"(c[0]), "+f"(c[1]), "+f"(c[2]), "+f"(c[3])
        : "r"(a0), "r"(a1), "r"(a2), "r"(a3), "r"(b0), "r"(b1));
}

// k permutation within 16: pairs (k, k+4) adjacent -> uint2 B-frag loads
__device__ __forceinline__ int KS(int k) {
    return ((k & 3) << 1) + ((k >> 2) & 1) + ((k >> 3) << 3);
}

__device__ __forceinline__ void cpa16(float* smem, const float* g) {
    uint32_t sa = (uint32_t)__cvta_generic_to_shared(smem);
    asm volatile("cp.async.cg.shared.global [%0], [%1], 16;" :: "r"(sa), "l"(g));
}

// ---------------- prep kernels ----------------------------------------------
__global__ void round_copy_k(const float* __restrict__ src, float* __restrict__ dst, int n) {
    int i = blockIdx.x * blockDim.x + threadIdx.x;
    if (i < n) dst[i] = __uint_as_float(f2tf32(src[i]));
}

__global__ void wprep_k(const float* __restrict__ src, int srcStride,
                        float* __restrict__ dst, int K) {
    int n = blockIdx.x;
    const float* s = src + (size_t)n * srcStride;
    float* d = dst + (size_t)n * K;
    for (int k = threadIdx.x; k < K; k += blockDim.x)
        d[(k & ~15) + KS(k & 15)] = __uint_as_float(f2tf32(s[k]));
}

__global__ void wbprep_k(const float* __restrict__ bWhh, const float* __restrict__ bWih,
                         float* __restrict__ dst) {
    int n = blockIdx.x;
    float* d = dst + (size_t)n * KBEAT;
    for (int k = threadIdx.x; k < KBEAT; k += blockDim.x) {
        float v = (k < HDIM) ? bWhh[(size_t)n * HDIM + k]
                             : bWih[(size_t)n * KBEAT + k];
        d[(k & ~15) + KS(k & 15)] = __uint_as_float(f2tf32(v));
    }
}

__global__ void zero_hc_k() {
    int i = blockIdx.x * blockDim.x + threadIdx.x;
    if (i < BATCH * HDIM) { g_h0[i] = 0.f; g_c[i] = 0.f; }
}

// ---------------- tf32 tensor GEMM w/ cp.async pipeline + fused LSTM --------
// 256 threads, 8 warps (2/SMSP), warp tile m32 x n32, BK=32, 3-stage pipeline.
template<bool LSTM, bool HAS_EXTRA>
__global__ void __launch_bounds__(256) tgemm_k(
    const float* __restrict__ A, int lda,
    const float* __restrict__ extra,
    const float* __restrict__ W, int ldw, int K,
    const float* __restrict__ bias_or_add, int addStride,
    float* __restrict__ out_or_h, int ldc,
    float* __restrict__ c_state,
    float* __restrict__ tanh_out, long long tanh_stride)
{
    extern __shared__ float sm[];
    float* Asm = sm;                          // STAGES * BM * APAD
    float* Bsm = sm + STAGES * BM * APAD;     // STAGES * BNC * BPAD

    const int tid  = threadIdx.x;
    const int wid  = tid >> 5;
    const int lane = tid & 31;
    const int wm   = wid >> 1;          // 0..3 : 32-row group
    const int wn   = wid & 1;           // 0..1 : 32-col group
    const int q    = lane & 3;
    const int rg   = lane >> 2;
    const int mblk = blockIdx.y * BM;
    const int nblk = blockIdx.x;

    // loader mapping: 256 threads, 8 floats (2 float4 columns) per 32-row chunk
    const int lrow = tid >> 3;          // 0..31
    const int lk4  = (tid & 7) << 2;    // 0,4,...,28

    const float* Ap[4];
    const float* Ep[4];
#pragma unroll
    for (int p = 0; p < 4; p++) {
        int r = mblk + lrow + 32 * p;
        Ap[p] = A + (size_t)r * lda + lk4;
        Ep[p] = HAS_EXTRA ? (extra + (size_t)r * (TBEAT * ODIM) + lk4) : (const float*)0;
    }
    const float* Bp[2];
#pragma unroll
    for (int p = 0; p < 2; p++) {
        int cn = lrow + 32 * p;
        int brow = LSTM ? ((cn >> 4) * HDIM + nblk * 16 + (cn & 15))
                        : (nblk * BNC + cn);
        Bp[p] = W + (size_t)brow * ldw + lk4;
    }
    int adst[4], bdst[2];
#pragma unroll
    for (int p = 0; p < 4; p++) adst[p] = (lrow + 32 * p) * APAD + lk4;
#pragma unroll
    for (int p = 0; p < 2; p++) bdst[p] = (lrow + 32 * p) * BPAD + lk4;

    const int nk = K / BK;

    auto issue = [&](int s, int it) {
        const int kt = it * BK;
        float* as = Asm + s * (BM * APAD);
        float* bs = Bsm + s * (BNC * BPAD);
#pragma unroll
        for (int p = 0; p < 4; p++) {
            const float* src = (HAS_EXTRA && kt >= HDIM) ? (Ep[p] + (kt - HDIM))
                                                         : (Ap[p] + kt);
            cpa16(&as[adst[p]], src);
        }
#pragma unroll
        for (int p = 0; p < 2; p++) cpa16(&bs[bdst[p]], Bp[p] + kt);
    };

    issue(0, 0);
    asm volatile("cp.async.commit_group;");
    issue(1, 1);
    asm volatile("cp.async.commit_group;");

    float acc[2][4][4];
#pragma unroll
    for (int a = 0; a < 2; a++)
#pragma unroll
        for (int b = 0; b < 4; b++)
#pragma unroll
            for (int cidx = 0; cidx < 4; cidx++) acc[a][b][cidx] = 0.f;

    int st = 0, st2 = 2;
    for (int it = 0; it < nk; ++it) {
        asm volatile("cp.async.wait_group 1;");
        __syncthreads();
        const float* as = Asm + st * (BM * APAD);
        const float* bs = Bsm + st * (BNC * BPAD);
#pragma unroll
        for (int G = 0; G < 4; ++G) {
            uint32_t a[2][4];
#pragma unroll
            for (int mt = 0; mt < 2; mt++) {
                const int r0 = (wm * 32 + mt * 16 + rg) * APAD + G * 8 + q;
                a[mt][0] = __float_as_uint(as[r0]);
                a[mt][1] = __float_as_uint(as[r0 + 8 * APAD]);
                a[mt][2] = __float_as_uint(as[r0 + 4]);
                a[mt][3] = __float_as_uint(as[r0 + 8 * APAD + 4]);
            }
            const int bcol = (G >> 1) * 16 + (G & 1) * 8 + 2 * q;
#pragma unroll
            for (int nt = 0; nt < 4; nt++) {
                const int cn0 = LSTM ? (nt * 16 + wn * 8) : (wn * 32 + nt * 8);
                const uint2 bb = *(const uint2*)&bs[(cn0 + rg) * BPAD + bcol];
#pragma unroll
                for (int mt = 0; mt < 2; mt++)
                    mma_tf32(acc[mt][nt], a[mt][0], a[mt][1], a[mt][2], a[mt][3],
                             bb.x, bb.y);
            }
        }
        if (it + 2 < nk) issue(st2, it + 2);
        asm volatile("cp.async.commit_group;");
        st = (st == STAGES - 1) ? 0 : st + 1;
        st2 = (st2 == STAGES - 1) ? 0 : st2 + 1;
    }
    asm volatile("cp.async.wait_group 0;");

    // ---------------- epilogue ----------------
    if (LSTM) {
#pragma unroll
        for (int mt = 0; mt < 2; mt++)
#pragma unroll
            for (int rs = 0; rs < 2; rs++)
#pragma unroll
                for (int ps = 0; ps < 2; ps++) {
                    const int r = mblk + wm * 32 + mt * 16 + rg + rs * 8;
                    const int j = nblk * 16 + wn * 8 + 2 * q + ps;
                    const int ai = rs * 2 + ps;
                    const float* ad = bias_or_add + (size_t)r * addStride + j;
                    float gi = acc[mt][0][ai] + ad[0];
                    float gf = acc[mt][1][ai] + ad[HDIM];
                    float gg = acc[mt][2][ai] + ad[2 * HDIM];
                    float go = acc[mt][3][ai] + ad[3 * HDIM];
                    const int ci = r * HDIM + j;
                    float cc = sigf(gf) * c_state[ci] + sigf(gi) * tanhf(gg);
                    c_state[ci] = cc;
                    float hh = sigf(go) * tanhf(cc);
                    out_or_h[ci] = __uint_as_float(f2tf32(hh));
                    tanh_out[(size_t)r * tanh_stride + j] =
                        __uint_as_float(f2tf32(tanhf(hh)));
                }
    } else {
#pragma unroll
        for (int mt = 0; mt < 2; mt++)
#pragma unroll
            for (int nt = 0; nt < 4; nt++)
#pragma unroll
                for (int rs = 0; rs < 2; rs++) {
                    const int r = mblk + wm * 32 + mt * 16 + rg + rs * 8;
                    const int col = nblk * BNC + wn * 32 + nt * 8 + 2 * q;
                    float2 o;
                    o.x = acc[mt][nt][rs * 2 + 0] + bias_or_add[col];
                    o.y = acc[mt][nt][rs * 2 + 1] + bias_or_add[col + 1];
                    *(float2*)&out_or_h[(size_t)r * ldc + col] = o;
                }
    }
}

// ---------------------------------------------------------------------------
extern "C" void kernel_launch(void* const* d_in, const int* in_sizes, int n_in,
                              void* d_out, int out_size) {
    const float* latent = (const float*)d_in[0];
    const float* inputs = (const float*)d_in[1];
    const float* mWih   = (const float*)d_in[2];
    const float* mWhh   = (const float*)d_in[3];
    const float* mb     = (const float*)d_in[4];
    const float* bWih   = (const float*)d_in[5];
    const float* bWhh   = (const float*)d_in[6];
    const float* bb     = (const float*)d_in[7];
    const float* linW   = (const float*)d_in[8];
    const float* linb   = (const float*)d_in[9];
    float* out = (float*)d_out;

    float *p_WbR, *p_mWihR, *p_mWhhR, *p_latWR, *p_linWR, *p_latentR, *p_inR;
    float *p_xg, *p_lat, *p_latproj, *p_h0, *p_h1, *p_c, *p_hall;
    cudaGetSymbolAddress((void**)&p_WbR, g_WbR);
    cudaGetSymbolAddress((void**)&p_mWihR, g_mWihR);
    cudaGetSymbolAddress((void**)&p_mWhhR, g_mWhhR);
    cudaGetSymbolAddress((void**)&p_latWR, g_latWR);
    cudaGetSymbolAddress((void**)&p_linWR, g_linWR);
    cudaGetSymbolAddress((void**)&p_latentR, g_latentR);
    cudaGetSymbolAddress((void**)&p_inR, g_inR);
    cudaGetSymbolAddress((void**)&p_xg, g_xg);
    cudaGetSymbolAddress((void**)&p_lat, g_lat);
    cudaGetSymbolAddress((void**)&p_latproj, g_latproj);
    cudaGetSymbolAddress((void**)&p_h0, g_h0);
    cudaGetSymbolAddress((void**)&p_h1, g_h1);
    cudaGetSymbolAddress((void**)&p_c, g_c);
    cudaGetSymbolAddress((void**)&p_hall, g_hall);

    cudaFuncSetAttribute(tgemm_k<false, false>,
                         cudaFuncAttributeMaxDynamicSharedMemorySize, SMEM_BYTES);
    cudaFuncSetAttribute(tgemm_k<true, false>,
                         cudaFuncAttributeMaxDynamicSharedMemorySize, SMEM_BYTES);
    cudaFuncSetAttribute(tgemm_k<true, true>,
                         cudaFuncAttributeMaxDynamicSharedMemorySize, SMEM_BYTES);

    // --- prep: round activations; round + k-permute all MMA weights ---
    round_copy_k<<<(BATCH * MEAS * INDIM + 255) / 256, 256>>>(latent, p_latentR,
                                                              BATCH * MEAS * INDIM);
    round_copy_k<<<(BATCH * TBEAT * ODIM + 255) / 256, 256>>>(inputs, p_inR,
                                                              BATCH * TBEAT * ODIM);
    wprep_k<<<G4, 256>>>(mWih, INDIM, p_mWihR, INDIM);
    wprep_k<<<G4, 256>>>(mWhh, HDIM, p_mWhhR, HDIM);
    wprep_k<<<G4, 256>>>(bWih, KBEAT, p_latWR, HDIM);
    wprep_k<<<ODIM, 256>>>(linW, HDIM, p_linWR, HDIM);
    wbprep_k<<<G4, 256>>>(bWhh, bWih, p_WbR);

    // --- measure input projection: xg = latent @ mWih^T + mb ---
    tgemm_k<false, false><<<dim3(G4 / BNC, (BATCH * MEAS) / BM), 256, SMEM_BYTES>>>(
        p_latentR, INDIM, nullptr, p_mWihR, INDIM, INDIM,
        mb, 0, p_xg, G4, nullptr, nullptr, 0);

    // --- measure LSTM (32 steps) ---
    zero_hc_k<<<(BATCH * HDIM) / 256, 256>>>();
    for (int t = 0; t < MEAS; t++) {
        const float* hi = (t & 1) ? p_h1 : p_h0;
        float* ho = (t & 1) ? p_h0 : p_h1;
        tgemm_k<true, false><<<dim3(HDIM / 16, BATCH / BM), 256, SMEM_BYTES>>>(
            hi, HDIM, nullptr, p_mWhhR, HDIM, HDIM,
            p_xg + t * G4, MEAS * G4, ho, 0, p_c,
            p_lat + t * HDIM, (long long)MEAS * HDIM);
    }

    // --- beat latent projection: latproj = lat @ bWih[:, :H]^T + bb ---
    tgemm_k<false, false><<<dim3(G4 / BNC, (BATCH * MEAS) / BM), 256, SMEM_BYTES>>>(
        p_lat, HDIM, nullptr, p_latWR, HDIM, HDIM,
        bb, 0, p_latproj, G4, nullptr, nullptr, 0);

    // --- beat LSTM (512 steps); inputs proj fused into GEMM K dim ---
    zero_hc_k<<<(BATCH * HDIM) / 256, 256>>>();
    for (int t = 0; t < TBEAT; t++) {
        const float* hi = (t & 1) ? p_h1 : p_h0;
        float* ho = (t & 1) ? p_h0 : p_h1;
        tgemm_k<true, true><<<dim3(HDIM / 16, BATCH / BM), 256, SMEM_BYTES>>>(
            hi, HDIM, p_inR + t * ODIM, p_WbR, KBEAT, KBEAT,
            p_latproj + (t >> 4) * G4, MEAS * G4, ho, 0, p_c,
            p_hall + t * HDIM, (long long)TBEAT * HDIM);
    }

    // --- output head: out = tanh(h_all) @ linW^T + linb ---
    tgemm_k<false, false><<<dim3(ODIM / BNC, (BATCH * TBEAT) / BM), 256, SMEM_BYTES>>>(
        p_hall, HDIM, nullptr, p_linWR, HDIM, HDIM,
        linb, 0, out, ODIM, nullptr, nullptr, 0);
}

// round 5
// speedup vs baseline: 4.0846x; 1.3709x over previous
#include <cuda_runtime.h>
#include <cuda_fp16.h>
#include <math.h>
#include <stdint.h>

#define BATCH 256
#define MEAS  32
#define TBEAT 512
#define INDIM 512
#define HDIM  1024
#define ODIM  128
#define G4    4096
#define KBEAT 1152

#define BM    128          // rows per CTA
#define BNC   64           // gate-cols per CTA (LSTM: 16 units x 4 gates)
#define BK    32
#define AP    40           // fp16 row pitch: 64B data + 16B pad -> 80B (ldmatrix conflict-free)
#define BP    40
#define STAGES 4
#define STAGE_HALFS (BM * AP + BNC * BP)
#define SMEM_BYTES  (STAGES * STAGE_HALFS * 2)

// ---------------- scratch (__device__ globals) -------------------------------
__device__ __half g_WbH[G4 * KBEAT];           // [bWhh | bWih_O] fp16
__device__ __half g_mWihH[G4 * INDIM];
__device__ __half g_mWhhH[G4 * HDIM];
__device__ __half g_latWH[G4 * HDIM];          // bWih[:, :H]
__device__ __half g_linWH[ODIM * HDIM];
__device__ __half g_latentH[BATCH * MEAS * INDIM];
__device__ __half g_inH[BATCH * TBEAT * ODIM];
__device__ float  g_xg[BATCH * MEAS * G4];
__device__ __half g_lat[BATCH * MEAS * HDIM];
__device__ float  g_latproj[BATCH * MEAS * G4];
__device__ __half g_h0[BATCH * HDIM];
__device__ __half g_h1[BATCH * HDIM];
__device__ float  g_c[BATCH * HDIM];
__device__ __half g_hall[BATCH * TBEAT * HDIM];

__device__ __forceinline__ float sigf(float x) { return 1.0f / (1.0f + expf(-x)); }

__device__ __forceinline__ void mma_f16(float* c, uint32_t a0, uint32_t a1,
                                        uint32_t a2, uint32_t a3,
                                        uint32_t b0, uint32_t b1) {
    asm volatile(
        "mma.sync.aligned.m16n8k16.row.col.f32.f16.f16.f32 "
        "{%0,%1,%2,%3}, {%4,%5,%6,%7}, {%8,%9}, {%0,%1,%2,%3};"
        : "+f"(c[0]), "+f"(c[1]), "+f"(c[2]), "+f"(c[3])
        : "r"(a0), "r"(a1), "r"(a2), "r"(a3), "r"(b0), "r"(b1));
}

__device__ __forceinline__ void ldsm4(uint32_t& r0, uint32_t& r1, uint32_t& r2,
                                      uint32_t& r3, uint32_t saddr) {
    asm volatile("ldmatrix.sync.aligned.m8n8.x4.shared.b16 {%0,%1,%2,%3}, [%4];"
                 : "=r"(r0), "=r"(r1), "=r"(r2), "=r"(r3) : "r"(saddr));
}

__device__ __forceinline__ void cpa16(uint32_t sa, const void* g) {
    asm volatile("cp.async.cg.shared.global [%0], [%1], 16;" :: "r"(sa), "l"(g));
}

// ---------------- prep kernels ----------------------------------------------
__global__ void f2h_k(const float* __restrict__ src, __half* __restrict__ dst, int n) {
    int i = blockIdx.x * blockDim.x + threadIdx.x;
    if (i < n) dst[i] = __float2half(src[i]);
}

// strided row gather + fp16 convert: dst[n*K + k] = src[n*srcStride + k]
__global__ void wprep_k(const float* __restrict__ src, int srcStride,
                        __half* __restrict__ dst, int K) {
    int n = blockIdx.x;
    const float* s = src + (size_t)n * srcStride;
    __half* d = dst + (size_t)n * K;
    for (int k = threadIdx.x; k < K; k += blockDim.x) d[k] = __float2half(s[k]);
}

// combined beat weights: k<1024 from bWhh, k>=1024 from bWih (col index = k)
__global__ void wbprep_k(const float* __restrict__ bWhh, const float* __restrict__ bWih,
                         __half* __restrict__ dst) {
    int n = blockIdx.x;
    __half* d = dst + (size_t)n * KBEAT;
    for (int k = threadIdx.x; k < KBEAT; k += blockDim.x) {
        float v = (k < HDIM) ? bWhh[(size_t)n * HDIM + k]
                             : bWih[(size_t)n * KBEAT + k];
        d[k] = __float2half(v);
    }
}

__global__ void zero_hc_k() {
    int i = blockIdx.x * blockDim.x + threadIdx.x;
    if (i < BATCH * HDIM) { g_h0[i] = __float2half(0.f); g_c[i] = 0.f; }
}

// ---------------- fp16 tensor GEMM: ldmatrix + cp.async + fused LSTM --------
// 256 threads, 8 warps, warp tile m32 x n32, BK=32, 4-stage pipeline.
// LSTM B smem row order: sr = wn*32 + gate*8 + u  (u = unit offset 0..7).
template<bool LSTM, bool HAS_EXTRA>
__global__ void __launch_bounds__(256, 2) tgemm_k(
    const __half* __restrict__ A, int lda,
    const __half* __restrict__ extra,
    const __half* __restrict__ W, int ldw, int K,
    const float* __restrict__ bias_or_add, int addStride,
    void* __restrict__ out_or_h, int ldc,
    float* __restrict__ c_state,
    __half* __restrict__ tanh_out, long long tanh_stride)
{
    extern __shared__ __half sm[];
    const uint32_t smb = (uint32_t)__cvta_generic_to_shared(sm);

    const int tid  = threadIdx.x;
    const int wid  = tid >> 5;
    const int lane = tid & 31;
    const int wm   = wid >> 1;          // 0..3 : 32-row group
    const int wn   = wid & 1;           // 0..1 : 32-col group
    const int q    = lane & 3;
    const int rg   = lane >> 2;
    const int mblk = blockIdx.y * BM;
    const int nblk = blockIdx.x;

    // ---- loader mapping ----
    // A: 512 16B-chunks (128 rows x 4); thread covers chunks tid and tid+256.
    const int rA0 = tid >> 2, rA1 = (tid >> 2) + 64;
    const int k8a = (tid & 3) << 3;
    const __half* Ap0 = A + (size_t)(mblk + rA0) * lda + k8a;
    const __half* Ap1 = A + (size_t)(mblk + rA1) * lda + k8a;
    const __half* Ep0 = HAS_EXTRA ? (extra + (size_t)(mblk + rA0) * (TBEAT * ODIM) + k8a) : (const __half*)0;
    const __half* Ep1 = HAS_EXTRA ? (extra + (size_t)(mblk + rA1) * (TBEAT * ODIM) + k8a) : (const __half*)0;
    const uint32_t adst0 = (rA0 * AP + k8a) * 2;
    const uint32_t adst1 = (rA1 * AP + k8a) * 2;
    // B: 256 chunks (64 rows x 4)
    const int sr  = tid >> 2;
    const int k8b = (tid & 3) << 3;
    const int brow = LSTM ? (((sr >> 3) & 3) * HDIM + nblk * 16 + (sr >> 5) * 8 + (sr & 7))
                          : (nblk * BNC + sr);
    const __half* Bp = W + (size_t)brow * ldw + k8b;
    const uint32_t bdst = (BM * AP + sr * BP + k8b) * 2;

    const int nk = K / BK;

    auto issue = [&](int s, int it) {
        const int kt = it * BK;
        const uint32_t sb = smb + s * (STAGE_HALFS * 2);
        if (HAS_EXTRA && kt >= HDIM) {
            cpa16(sb + adst0, Ep0 + (kt - HDIM));
            cpa16(sb + adst1, Ep1 + (kt - HDIM));
        } else {
            cpa16(sb + adst0, Ap0 + kt);
            cpa16(sb + adst1, Ap1 + kt);
        }
        cpa16(sb + bdst, Bp + kt);
    };

    issue(0, 0); asm volatile("cp.async.commit_group;");
    issue(1, 1); asm volatile("cp.async.commit_group;");
    issue(2, 2); asm volatile("cp.async.commit_group;");

    // ---- per-thread ldmatrix source offsets (in halfs) ----
    const uint32_t aoff = (uint32_t)((wm * 32 + (lane & 15)) * AP + ((lane >> 4) << 3));
    const uint32_t boff = (uint32_t)(BM * AP +
        (wn * 32 + (lane & 7) + ((lane >> 4) << 3)) * BP + (((lane >> 3) & 1) << 3));

    float acc[2][4][4];
#pragma unroll
    for (int a = 0; a < 2; a++)
#pragma unroll
        for (int b = 0; b < 4; b++)
#pragma unroll
            for (int cc = 0; cc < 4; cc++) acc[a][b][cc] = 0.f;

    int st = 0;
    for (int it = 0; it < nk; ++it) {
        asm volatile("cp.async.wait_group 2;");
        __syncthreads();
        const uint32_t sb = smb + st * (STAGE_HALFS * 2);
#pragma unroll
        for (int ko = 0; ko < BK; ko += 16) {
            uint32_t a[2][4];
#pragma unroll
            for (int mt = 0; mt < 2; mt++)
                ldsm4(a[mt][0], a[mt][1], a[mt][2], a[mt][3],
                      sb + (aoff + mt * 16 * AP + ko) * 2);
            uint32_t bfr[4][2];
#pragma unroll
            for (int gp = 0; gp < 2; gp++)
                ldsm4(bfr[gp * 2][0], bfr[gp * 2][1], bfr[gp * 2 + 1][0], bfr[gp * 2 + 1][1],
                      sb + (boff + gp * 16 * BP + ko) * 2);
#pragma unroll
            for (int nt = 0; nt < 4; nt++)
#pragma unroll
                for (int mt = 0; mt < 2; mt++)
                    mma_f16(acc[mt][nt], a[mt][0], a[mt][1], a[mt][2], a[mt][3],
                            bfr[nt][0], bfr[nt][1]);
        }
        if (it + 3 < nk) issue((it + 3) & 3, it + 3);
        asm volatile("cp.async.commit_group;");
        st = (st + 1) & 3;
    }
    asm volatile("cp.async.wait_group 0;");

    // ---------------- epilogue ----------------
    if (LSTM) {
        __half* h_out = (__half*)out_or_h;
#pragma unroll
        for (int mt = 0; mt < 2; mt++)
#pragma unroll
            for (int rs = 0; rs < 2; rs++)
#pragma unroll
                for (int ps = 0; ps < 2; ps++) {
                    const int r = mblk + wm * 32 + mt * 16 + rg + rs * 8;
                    const int j = nblk * 16 + wn * 8 + 2 * q + ps;
                    const int ai = rs * 2 + ps;
                    const float* ad = bias_or_add + (size_t)r * addStride + j;
                    float gi = acc[mt][0][ai] + ad[0];
                    float gf = acc[mt][1][ai] + ad[HDIM];
                    float gg = acc[mt][2][ai] + ad[2 * HDIM];
                    float go = acc[mt][3][ai] + ad[3 * HDIM];
                    const int ci = r * HDIM + j;
                    float cc = sigf(gf) * c_state[ci] + sigf(gi) * tanhf(gg);
                    c_state[ci] = cc;
                    float hh = sigf(go) * tanhf(cc);
                    h_out[ci] = __float2half(hh);
                    tanh_out[(size_t)r * tanh_stride + j] = __float2half(tanhf(hh));
                }
    } else {
        float* C = (float*)out_or_h;
#pragma unroll
        for (int mt = 0; mt < 2; mt++)
#pragma unroll
            for (int nt = 0; nt < 4; nt++)
#pragma unroll
                for (int rs = 0; rs < 2; rs++) {
                    const int r = mblk + wm * 32 + mt * 16 + rg + rs * 8;
                    const int col = nblk * BNC + wn * 32 + nt * 8 + 2 * q;
                    float2 o;
                    o.x = acc[mt][nt][rs * 2 + 0] + bias_or_add[col];
                    o.y = acc[mt][nt][rs * 2 + 1] + bias_or_add[col + 1];
                    *(float2*)&C[(size_t)r * ldc + col] = o;
                }
    }
}

// ---------------------------------------------------------------------------
extern "C" void kernel_launch(void* const* d_in, const int* in_sizes, int n_in,
                              void* d_out, int out_size) {
    const float* latent = (const float*)d_in[0];
    const float* inputs = (const float*)d_in[1];
    const float* mWih   = (const float*)d_in[2];
    const float* mWhh   = (const float*)d_in[3];
    const float* mb     = (const float*)d_in[4];
    const float* bWih   = (const float*)d_in[5];
    const float* bWhh   = (const float*)d_in[6];
    const float* bb     = (const float*)d_in[7];
    const float* linW   = (const float*)d_in[8];
    const float* linb   = (const float*)d_in[9];
    float* out = (float*)d_out;

    __half *p_WbH, *p_mWihH, *p_mWhhH, *p_latWH, *p_linWH, *p_latentH, *p_inH;
    __half *p_lat, *p_h0, *p_h1, *p_hall;
    float *p_xg, *p_latproj, *p_c;
    cudaGetSymbolAddress((void**)&p_WbH, g_WbH);
    cudaGetSymbolAddress((void**)&p_mWihH, g_mWihH);
    cudaGetSymbolAddress((void**)&p_mWhhH, g_mWhhH);
    cudaGetSymbolAddress((void**)&p_latWH, g_latWH);
    cudaGetSymbolAddress((void**)&p_linWH, g_linWH);
    cudaGetSymbolAddress((void**)&p_latentH, g_latentH);
    cudaGetSymbolAddress((void**)&p_inH, g_inH);
    cudaGetSymbolAddress((void**)&p_xg, g_xg);
    cudaGetSymbolAddress((void**)&p_lat, g_lat);
    cudaGetSymbolAddress((void**)&p_latproj, g_latproj);
    cudaGetSymbolAddress((void**)&p_h0, g_h0);
    cudaGetSymbolAddress((void**)&p_h1, g_h1);
    cudaGetSymbolAddress((void**)&p_c, g_c);
    cudaGetSymbolAddress((void**)&p_hall, g_hall);

    cudaFuncSetAttribute(tgemm_k<false, false>,
                         cudaFuncAttributeMaxDynamicSharedMemorySize, SMEM_BYTES);
    cudaFuncSetAttribute(tgemm_k<true, false>,
                         cudaFuncAttributeMaxDynamicSharedMemorySize, SMEM_BYTES);
    cudaFuncSetAttribute(tgemm_k<true, true>,
                         cudaFuncAttributeMaxDynamicSharedMemorySize, SMEM_BYTES);

    // --- prep: fp16 conversions ---
    f2h_k<<<(BATCH * MEAS * INDIM + 255) / 256, 256>>>(latent, p_latentH,
                                                       BATCH * MEAS * INDIM);
    f2h_k<<<(BATCH * TBEAT * ODIM + 255) / 256, 256>>>(inputs, p_inH,
                                                       BATCH * TBEAT * ODIM);
    wprep_k<<<G4, 256>>>(mWih, INDIM, p_mWihH, INDIM);
    wprep_k<<<G4, 256>>>(mWhh, HDIM, p_mWhhH, HDIM);
    wprep_k<<<G4, 256>>>(bWih, KBEAT, p_latWH, HDIM);
    wprep_k<<<ODIM, 256>>>(linW, HDIM, p_linWH, HDIM);
    wbprep_k<<<G4, 256>>>(bWhh, bWih, p_WbH);

    // --- measure input projection: xg = latent @ mWih^T + mb ---
    tgemm_k<false, false><<<dim3(G4 / BNC, (BATCH * MEAS) / BM), 256, SMEM_BYTES>>>(
        p_latentH, INDIM, nullptr, p_mWihH, INDIM, INDIM,
        mb, 0, p_xg, G4, nullptr, nullptr, 0);

    // --- measure LSTM (32 steps) ---
    zero_hc_k<<<(BATCH * HDIM) / 256, 256>>>();
    for (int t = 0; t < MEAS; t++) {
        const __half* hi = (t & 1) ? p_h1 : p_h0;
        __half* ho = (t & 1) ? p_h0 : p_h1;
        tgemm_k<true, false><<<dim3(HDIM / 16, BATCH / BM), 256, SMEM_BYTES>>>(
            hi, HDIM, nullptr, p_mWhhH, HDIM, HDIM,
            p_xg + t * G4, MEAS * G4, ho, 0, p_c,
            p_lat + t * HDIM, (long long)MEAS * HDIM);
    }

    // --- beat latent projection: latproj = lat @ bWih[:, :H]^T + bb ---
    tgemm_k<false, false><<<dim3(G4 / BNC, (BATCH * MEAS) / BM), 256, SMEM_BYTES>>>(
        p_lat, HDIM, nullptr, p_latWH, HDIM, HDIM,
        bb, 0, p_latproj, G4, nullptr, nullptr, 0);

    // --- beat LSTM (512 steps); inputs proj fused into GEMM K dim ---
    zero_hc_k<<<(BATCH * HDIM) / 256, 256>>>();
    for (int t = 0; t < TBEAT; t++) {
        const __half* hi = (t & 1) ? p_h1 : p_h0;
        __half* ho = (t & 1) ? p_h0 : p_h1;
        tgemm_k<true, true><<<dim3(HDIM / 16, BATCH / BM), 256, SMEM_BYTES>>>(
            hi, HDIM, p_inH + t * ODIM, p_WbH, KBEAT, KBEAT,
            p_latproj + (t >> 4) * G4, MEAS * G4, ho, 0, p_c,
            p_hall + t * HDIM, (long long)TBEAT * HDIM);
    }

    // --- output head: out = tanh(h_all) @ linW^T + linb ---
    tgemm_k<false, false><<<dim3(ODIM / BNC, (BATCH * TBEAT) / BM), 256, SMEM_BYTES>>>(
        p_hall, HDIM, nullptr, p_linWH, HDIM, HDIM,
        linb, 0, out, ODIM, nullptr, nullptr, 0);
}

// round 6
// speedup vs baseline: 5.3562x; 1.3113x over previous
#include <cuda_runtime.h>
#include <cuda_fp16.h>
#include <math.h>
#include <stdint.h>

#define BATCH 256
#define MEAS  32
#define TBEAT 512
#define INDIM 512
#define HDIM  1024
#define ODIM  128
#define G4    4096
#define KBEAT 1152

#define BM    128
#define BNC   64
#define BK    32
#define AP    40            // A stage pitch (halfs): 80B rows, ldmatrix conflict-free
#define GRID_CTAS 128

// ---------------- scratch ----------------------------------------------------
__device__ __half g_WbH[G4 * KBEAT];
__device__ __half g_mWihH[G4 * INDIM];
__device__ __half g_mWhhH[G4 * HDIM];
__device__ __half g_latWH[G4 * HDIM];
__device__ __half g_linWH[ODIM * HDIM];
__device__ __half g_latentH[BATCH * MEAS * INDIM];
__device__ __half g_inH[BATCH * TBEAT * ODIM];
__device__ float  g_xg[BATCH * MEAS * G4];
__device__ __half g_lat[BATCH * MEAS * HDIM];
__device__ float  g_latproj[BATCH * MEAS * G4];
__device__ __half g_h0[BATCH * HDIM];
__device__ __half g_h1[BATCH * HDIM];
__device__ __half g_hall[BATCH * TBEAT * HDIM];
__device__ unsigned g_bar;

__device__ __forceinline__ float sigf(float x) { return 1.0f / (1.0f + expf(-x)); }

__device__ __forceinline__ void mma_f16(float* c, uint32_t a0, uint32_t a1,
                                        uint32_t a2, uint32_t a3,
                                        uint32_t b0, uint32_t b1) {
    asm volatile(
        "mma.sync.aligned.m16n8k16.row.col.f32.f16.f16.f32 "
        "{%0,%1,%2,%3}, {%4,%5,%6,%7}, {%8,%9}, {%0,%1,%2,%3};"
        : "+f"(c[0]), "+f"(c[1]), "+f"(c[2]), "+f"(c[3])
        : "r"(a0), "r"(a1), "r"(a2), "r"(a3), "r"(b0), "r"(b1));
}

__device__ __forceinline__ void ldsm4(uint32_t& r0, uint32_t& r1, uint32_t& r2,
                                      uint32_t& r3, uint32_t saddr) {
    asm volatile("ldmatrix.sync.aligned.m8n8.x4.shared.b16 {%0,%1,%2,%3}, [%4];"
                 : "=r"(r0), "=r"(r1), "=r"(r2), "=r"(r3) : "r"(saddr));
}

__device__ __forceinline__ void cpa16(uint32_t sa, const void* g) {
    asm volatile("cp.async.cg.shared.global [%0], [%1], 16;" :: "r"(sa), "l"(g));
}

// ---------------- prep kernels ----------------------------------------------
__global__ void f2h_k(const float* __restrict__ src, __half* __restrict__ dst, int n) {
    int i = blockIdx.x * blockDim.x + threadIdx.x;
    if (i < n) dst[i] = __float2half(src[i]);
}

__global__ void wprep_k(const float* __restrict__ src, int srcStride,
                        __half* __restrict__ dst, int K) {
    int n = blockIdx.x;
    const float* s = src + (size_t)n * srcStride;
    __half* d = dst + (size_t)n * K;
    for (int k = threadIdx.x; k < K; k += blockDim.x) d[k] = __float2half(s[k]);
}

__global__ void wbprep_k(const float* __restrict__ bWhh, const float* __restrict__ bWih,
                         __half* __restrict__ dst) {
    int n = blockIdx.x;
    __half* d = dst + (size_t)n * KBEAT;
    for (int k = threadIdx.x; k < KBEAT; k += blockDim.x) {
        float v = (k < HDIM) ? bWhh[(size_t)n * HDIM + k]
                             : bWih[(size_t)n * KBEAT + k];
        d[k] = __float2half(v);
    }
}

__global__ void zero_h_k() {
    int i = blockIdx.x * blockDim.x + threadIdx.x;
    if (i < BATCH * HDIM) g_h0[i] = __float2half(0.f);
    if (i == 0) g_bar = 0u;
}

// ---------------- persistent fused LSTM recurrence ---------------------------
// Grid 64x2 = 128 CTAs (all co-resident). Weight tile (64 gate-rows x KDIM fp16)
// lives in SMEM for all NSTEPS. c-state lives in registers. Device-wide
// release/acquire barrier between steps.
template<int KDIM, bool HAS_EXTRA, int NSTEPS>
__global__ void __launch_bounds__(256, 1) lstm_persist_k(
    const __half* __restrict__ extra,          // beat inputs (row-major, TBEAT*ODIM)
    const __half* __restrict__ W,              // rows gate*HDIM+unit, KDIM cols
    const float* __restrict__ add_base,        // xg / latproj (row stride MEAS*G4)
    __half* __restrict__ hb0, __half* __restrict__ hb1,
    __half* __restrict__ tanh_out, long long tanh_rstride)
{
    constexpr int WP = KDIM + 8;               // resident W pitch (halfs)
    constexpr int nk = KDIM / BK;
    extern __shared__ __half sm[];
    const uint32_t wsmb = (uint32_t)__cvta_generic_to_shared(sm);
    const uint32_t asmb = wsmb + 64 * WP * 2;

    const int tid  = threadIdx.x;
    const int wid  = tid >> 5;
    const int lane = tid & 31;
    const int wm   = wid >> 1;
    const int wn   = wid & 1;
    const int q    = lane & 3;
    const int rg   = lane >> 2;
    const int nblk = blockIdx.x;
    const int mblk = blockIdx.y * BM;

    // ---- load resident W tile (gate-major smem rows) ----
    for (int idx = tid; idx < 64 * (KDIM / 8); idx += 256) {
        int sr = idx / (KDIM / 8);
        int k8 = (idx % (KDIM / 8)) * 8;
        int brow = ((sr >> 3) & 3) * HDIM + nblk * 16 + ((sr >> 5) << 3) + (sr & 7);
        cpa16(wsmb + (uint32_t)(sr * WP + k8) * 2, W + (size_t)brow * KDIM + k8);
    }
    asm volatile("cp.async.commit_group;");
    asm volatile("cp.async.wait_group 0;");
    __syncthreads();

    // ---- A loader mapping ----
    const int rA0 = tid >> 2, rA1 = rA0 + 64;
    const int k8a = (tid & 3) << 3;
    const uint32_t adst0 = (uint32_t)(rA0 * AP + k8a) * 2;
    const uint32_t adst1 = (uint32_t)(rA1 * AP + k8a) * 2;
    const __half* ex0 = HAS_EXTRA ?
        (extra + (size_t)(mblk + rA0) * (TBEAT * ODIM) + k8a) : (const __half*)0;
    const __half* ex1 = HAS_EXTRA ?
        (extra + (size_t)(mblk + rA1) * (TBEAT * ODIM) + k8a) : (const __half*)0;

    // ---- ldmatrix offsets (bytes, relative to region bases) ----
    const uint32_t aoff = (uint32_t)((wm * 32 + (lane & 15)) * AP + ((lane >> 4) << 3)) * 2;
    const uint32_t bbase = wsmb +
        (uint32_t)((wn * 32 + (lane & 7) + ((lane >> 4) << 3)) * WP + (((lane >> 3) & 1) << 3)) * 2;

    float creg[8];
#pragma unroll
    for (int i = 0; i < 8; i++) creg[i] = 0.f;

    unsigned barTarget = 0;

#pragma unroll 1
    for (int t = 0; t < NSTEPS; ++t) {
        const __half* hin = (t & 1) ? hb1 : hb0;
        __half* hout = (t & 1) ? hb0 : hb1;
        const __half* hA0 = hin + (size_t)(mblk + rA0) * HDIM + k8a;
        const __half* hA1 = hin + (size_t)(mblk + rA1) * HDIM + k8a;
        const int tOD = t * ODIM;

        auto issue = [&](int s, int it) {
            const int kt = it * BK;
            const uint32_t sb = asmb + (uint32_t)s * (BM * AP * 2);
            if (HAS_EXTRA && kt >= HDIM) {
                cpa16(sb + adst0, ex0 + tOD + (kt - HDIM));
                cpa16(sb + adst1, ex1 + tOD + (kt - HDIM));
            } else {
                cpa16(sb + adst0, hA0 + kt);
                cpa16(sb + adst1, hA1 + kt);
            }
        };

        issue(0, 0); asm volatile("cp.async.commit_group;");
        issue(1, 1); asm volatile("cp.async.commit_group;");
        issue(2, 2); asm volatile("cp.async.commit_group;");

        float acc[2][4][4];
#pragma unroll
        for (int a = 0; a < 2; a++)
#pragma unroll
            for (int b = 0; b < 4; b++)
#pragma unroll
                for (int cc = 0; cc < 4; cc++) acc[a][b][cc] = 0.f;

#pragma unroll 1
        for (int it = 0; it < nk; ++it) {
            asm volatile("cp.async.wait_group 2;");
            __syncthreads();
            const uint32_t ab = asmb + (uint32_t)(it & 3) * (BM * AP * 2);
            const uint32_t kglob = (uint32_t)(it * BK) * 2;
#pragma unroll
            for (int ko = 0; ko < 2; ++ko) {
                uint32_t a[2][4];
#pragma unroll
                for (int mt = 0; mt < 2; mt++)
                    ldsm4(a[mt][0], a[mt][1], a[mt][2], a[mt][3],
                          ab + aoff + (uint32_t)(mt * 16 * AP + ko * 16) * 2);
                uint32_t bfr[4][2];
#pragma unroll
                for (int gp = 0; gp < 2; gp++)
                    ldsm4(bfr[gp * 2][0], bfr[gp * 2][1],
                          bfr[gp * 2 + 1][0], bfr[gp * 2 + 1][1],
                          bbase + (uint32_t)(gp * 16 * WP) * 2 + kglob + (uint32_t)(ko * 16) * 2);
#pragma unroll
                for (int nt = 0; nt < 4; nt++)
#pragma unroll
                    for (int mt = 0; mt < 2; mt++)
                        mma_f16(acc[mt][nt], a[mt][0], a[mt][1], a[mt][2], a[mt][3],
                                bfr[nt][0], bfr[nt][1]);
            }
            if (it + 3 < nk) issue((it + 3) & 3, it + 3);
            asm volatile("cp.async.commit_group;");
        }
        asm volatile("cp.async.wait_group 0;");

        // ---- fused LSTM epilogue (c in registers) ----
        const float* adp = add_base + (size_t)(HAS_EXTRA ? (t >> 4) : t) * G4;
#pragma unroll
        for (int mt = 0; mt < 2; mt++)
#pragma unroll
            for (int rs = 0; rs < 2; rs++)
#pragma unroll
                for (int ps = 0; ps < 2; ps++) {
                    const int r = mblk + wm * 32 + mt * 16 + rg + rs * 8;
                    const int j = nblk * 16 + wn * 8 + 2 * q + ps;
                    const int ai = rs * 2 + ps;
                    const float* ad = adp + (size_t)r * (MEAS * G4) + j;
                    float gi = acc[mt][0][ai] + ad[0];
                    float gf = acc[mt][1][ai] + ad[HDIM];
                    float gg = acc[mt][2][ai] + ad[2 * HDIM];
                    float go = acc[mt][3][ai] + ad[3 * HDIM];
                    const int ci = mt * 4 + rs * 2 + ps;
                    float cc = sigf(gf) * creg[ci] + sigf(gi) * tanhf(gg);
                    creg[ci] = cc;
                    float hh = sigf(go) * tanhf(cc);
                    hout[r * HDIM + j] = __float2half(hh);
                    tanh_out[(size_t)r * tanh_rstride + (size_t)t * HDIM + j] =
                        __float2half(tanhf(hh));
                }

        // ---- device-wide barrier between steps ----
        if (t + 1 < NSTEPS) {
            __threadfence();
            __syncthreads();
            if (tid == 0) {
                unsigned x;
                asm volatile("atom.add.release.gpu.global.u32 %0, [%1], 1;"
                             : "=r"(x) : "l"(&g_bar));
                barTarget += GRID_CTAS;
                unsigned v;
                do {
                    asm volatile("ld.acquire.gpu.global.u32 %0, [%1];"
                                 : "=r"(v) : "l"(&g_bar));
                } while (v < barTarget);
            }
            __syncthreads();
        }
    }
}

// ---------------- plain fp16 tensor GEMM (non-recurrent projections) --------
#define GAP 40
#define GBP 40
#define GSTAGE_HALFS (BM * GAP + BNC * GBP)
#define GSMEM_BYTES  (4 * GSTAGE_HALFS * 2)

__global__ void __launch_bounds__(256, 2) gemm_k(
    const __half* __restrict__ A, int lda,
    const __half* __restrict__ W, int ldw, int K,
    const float* __restrict__ bias,
    float* __restrict__ C, int ldc)
{
    extern __shared__ __half sm[];
    const uint32_t smb = (uint32_t)__cvta_generic_to_shared(sm);

    const int tid  = threadIdx.x;
    const int wid  = tid >> 5;
    const int lane = tid & 31;
    const int wm   = wid >> 1;
    const int wn   = wid & 1;
    const int q    = lane & 3;
    const int rg   = lane >> 2;
    const int mblk = blockIdx.y * BM;
    const int nblk = blockIdx.x;

    const int rA0 = tid >> 2, rA1 = rA0 + 64;
    const int k8a = (tid & 3) << 3;
    const __half* Ap0 = A + (size_t)(mblk + rA0) * lda + k8a;
    const __half* Ap1 = A + (size_t)(mblk + rA1) * lda + k8a;
    const uint32_t adst0 = (uint32_t)(rA0 * GAP + k8a) * 2;
    const uint32_t adst1 = (uint32_t)(rA1 * GAP + k8a) * 2;
    const int sr  = tid >> 2;
    const int k8b = (tid & 3) << 3;
    const __half* Bp = W + (size_t)(nblk * BNC + sr) * ldw + k8b;
    const uint32_t bdst = (uint32_t)(BM * GAP + sr * GBP + k8b) * 2;

    const int nk = K / BK;
    auto issue = [&](int s, int it) {
        const int kt = it * BK;
        const uint32_t sb = smb + (uint32_t)s * (GSTAGE_HALFS * 2);
        cpa16(sb + adst0, Ap0 + kt);
        cpa16(sb + adst1, Ap1 + kt);
        cpa16(sb + bdst, Bp + kt);
    };
    issue(0, 0); asm volatile("cp.async.commit_group;");
    issue(1, 1); asm volatile("cp.async.commit_group;");
    issue(2, 2); asm volatile("cp.async.commit_group;");

    const uint32_t aoff = (uint32_t)((wm * 32 + (lane & 15)) * GAP + ((lane >> 4) << 3)) * 2;
    const uint32_t boff = (uint32_t)(BM * GAP +
        (wn * 32 + (lane & 7) + ((lane >> 4) << 3)) * GBP + (((lane >> 3) & 1) << 3)) * 2;

    float acc[2][4][4];
#pragma unroll
    for (int a = 0; a < 2; a++)
#pragma unroll
        for (int b = 0; b < 4; b++)
#pragma unroll
            for (int cc = 0; cc < 4; cc++) acc[a][b][cc] = 0.f;

    int st = 0;
    for (int it = 0; it < nk; ++it) {
        asm volatile("cp.async.wait_group 2;");
        __syncthreads();
        const uint32_t sb = smb + (uint32_t)st * (GSTAGE_HALFS * 2);
#pragma unroll
        for (int ko = 0; ko < 2; ++ko) {
            uint32_t a[2][4];
#pragma unroll
            for (int mt = 0; mt < 2; mt++)
                ldsm4(a[mt][0], a[mt][1], a[mt][2], a[mt][3],
                      sb + aoff + (uint32_t)(mt * 16 * GAP + ko * 16) * 2);
            uint32_t bfr[4][2];
#pragma unroll
            for (int gp = 0; gp < 2; gp++)
                ldsm4(bfr[gp * 2][0], bfr[gp * 2][1],
                      bfr[gp * 2 + 1][0], bfr[gp * 2 + 1][1],
                      sb + boff + (uint32_t)(gp * 16 * GBP + ko * 16) * 2);
#pragma unroll
            for (int nt = 0; nt < 4; nt++)
#pragma unroll
                for (int mt = 0; mt < 2; mt++)
                    mma_f16(acc[mt][nt], a[mt][0], a[mt][1], a[mt][2], a[mt][3],
                            bfr[nt][0], bfr[nt][1]);
        }
        if (it + 3 < nk) issue((it + 3) & 3, it + 3);
        asm volatile("cp.async.commit_group;");
        st = (st + 1) & 3;
    }
    asm volatile("cp.async.wait_group 0;");

#pragma unroll
    for (int mt = 0; mt < 2; mt++)
#pragma unroll
        for (int nt = 0; nt < 4; nt++)
#pragma unroll
            for (int rs = 0; rs < 2; rs++) {
                const int r = mblk + wm * 32 + mt * 16 + rg + rs * 8;
                const int col = nblk * BNC + wn * 32 + nt * 8 + 2 * q;
                float2 o;
                o.x = acc[mt][nt][rs * 2 + 0] + bias[col];
                o.y = acc[mt][nt][rs * 2 + 1] + bias[col + 1];
                *(float2*)&C[(size_t)r * ldc + col] = o;
            }
}

// head variant writing fp32 out directly (same as gemm_k; C=out): reuse gemm_k.

// ---------------------------------------------------------------------------
extern "C" void kernel_launch(void* const* d_in, const int* in_sizes, int n_in,
                              void* d_out, int out_size) {
    const float* latent = (const float*)d_in[0];
    const float* inputs = (const float*)d_in[1];
    const float* mWih   = (const float*)d_in[2];
    const float* mWhh   = (const float*)d_in[3];
    const float* mb     = (const float*)d_in[4];
    const float* bWih   = (const float*)d_in[5];
    const float* bWhh   = (const float*)d_in[6];
    const float* bb     = (const float*)d_in[7];
    const float* linW   = (const float*)d_in[8];
    const float* linb   = (const float*)d_in[9];
    float* out = (float*)d_out;

    __half *p_WbH, *p_mWihH, *p_mWhhH, *p_latWH, *p_linWH, *p_latentH, *p_inH;
    __half *p_lat, *p_h0, *p_h1, *p_hall;
    float *p_xg, *p_latproj;
    cudaGetSymbolAddress((void**)&p_WbH, g_WbH);
    cudaGetSymbolAddress((void**)&p_mWihH, g_mWihH);
    cudaGetSymbolAddress((void**)&p_mWhhH, g_mWhhH);
    cudaGetSymbolAddress((void**)&p_latWH, g_latWH);
    cudaGetSymbolAddress((void**)&p_linWH, g_linWH);
    cudaGetSymbolAddress((void**)&p_latentH, g_latentH);
    cudaGetSymbolAddress((void**)&p_inH, g_inH);
    cudaGetSymbolAddress((void**)&p_xg, g_xg);
    cudaGetSymbolAddress((void**)&p_lat, g_lat);
    cudaGetSymbolAddress((void**)&p_latproj, g_latproj);
    cudaGetSymbolAddress((void**)&p_h0, g_h0);
    cudaGetSymbolAddress((void**)&p_h1, g_h1);
    cudaGetSymbolAddress((void**)&p_hall, g_hall);

    const int measSmem = (64 * (HDIM + 8) + 4 * BM * AP) * 2;
    const int beatSmem = (64 * (KBEAT + 8) + 4 * BM * AP) * 2;
    cudaFuncSetAttribute(lstm_persist_k<HDIM, false, MEAS>,
                         cudaFuncAttributeMaxDynamicSharedMemorySize, measSmem);
    cudaFuncSetAttribute(lstm_persist_k<KBEAT, true, TBEAT>,
                         cudaFuncAttributeMaxDynamicSharedMemorySize, beatSmem);
    cudaFuncSetAttribute(gemm_k, cudaFuncAttributeMaxDynamicSharedMemorySize,
                         GSMEM_BYTES);

    // --- prep ---
    f2h_k<<<(BATCH * MEAS * INDIM + 255) / 256, 256>>>(latent, p_latentH,
                                                       BATCH * MEAS * INDIM);
    f2h_k<<<(BATCH * TBEAT * ODIM + 255) / 256, 256>>>(inputs, p_inH,
                                                       BATCH * TBEAT * ODIM);
    wprep_k<<<G4, 256>>>(mWih, INDIM, p_mWihH, INDIM);
    wprep_k<<<G4, 256>>>(mWhh, HDIM, p_mWhhH, HDIM);
    wprep_k<<<G4, 256>>>(bWih, KBEAT, p_latWH, HDIM);
    wprep_k<<<ODIM, 256>>>(linW, HDIM, p_linWH, HDIM);
    wbprep_k<<<G4, 256>>>(bWhh, bWih, p_WbH);

    // --- measure input projection: xg = latent @ mWih^T + mb ---
    gemm_k<<<dim3(G4 / BNC, (BATCH * MEAS) / BM), 256, GSMEM_BYTES>>>(
        p_latentH, INDIM, p_mWihH, INDIM, INDIM, mb, p_xg, G4);

    // --- measure LSTM: one persistent kernel, 32 steps ---
    zero_h_k<<<(BATCH * HDIM) / 256, 256>>>();
    lstm_persist_k<HDIM, false, MEAS><<<dim3(64, 2), 256, measSmem>>>(
        nullptr, p_mWhhH, p_xg, p_h0, p_h1, p_lat, (long long)MEAS * HDIM);

    // --- beat latent projection: latproj = lat @ bWih[:, :H]^T + bb ---
    gemm_k<<<dim3(G4 / BNC, (BATCH * MEAS) / BM), 256, GSMEM_BYTES>>>(
        p_lat, HDIM, p_latWH, HDIM, HDIM, bb, p_latproj, G4);

    // --- beat LSTM: one persistent kernel, 512 steps ---
    zero_h_k<<<(BATCH * HDIM) / 256, 256>>>();
    lstm_persist_k<KBEAT, true, TBEAT><<<dim3(64, 2), 256, beatSmem>>>(
        p_inH, p_WbH, p_latproj, p_h0, p_h1, p_hall, (long long)TBEAT * HDIM);

    // --- output head: out = tanh(h_all) @ linW^T + linb ---
    gemm_k<<<dim3(ODIM / BNC, (BATCH * TBEAT) / BM), 256, GSMEM_BYTES>>>(
        p_hall, HDIM, p_linWH, HDIM, HDIM, linb, out, ODIM);
}

// round 8
// speedup vs baseline: 6.1020x; 1.1392x over previous
#include <cuda_runtime.h>
#include <cuda_fp16.h>
#include <math.h>
#include <stdint.h>

#define BATCH 256
#define MEAS  32
#define TBEAT 512
#define INDIM 512
#define HDIM  1024
#define ODIM  128
#define G4    4096
#define KBEAT 1152
#define GRID_CTAS 128

#define BM    128
#define BNC   64
#define AP    72            // A stage pitch (halfs): 144B rows, ldmatrix conflict-free
#define PBK   64            // persistent-kernel K tile

// ---------------- scratch ----------------------------------------------------
__device__ __half g_WbH[G4 * KBEAT];
__device__ __half g_mWihH[G4 * INDIM];
__device__ __half g_mWhhH[G4 * HDIM];
__device__ __half g_latWH[G4 * HDIM];
__device__ __half g_linWH[ODIM * HDIM];
__device__ __half g_latentH[BATCH * MEAS * INDIM];
__device__ __half g_inH[BATCH * TBEAT * ODIM];
__device__ float  g_xg[BATCH * MEAS * G4];
__device__ __half g_lat[BATCH * MEAS * HDIM];
__device__ float  g_latproj[BATCH * MEAS * G4];
__device__ __half g_h0[BATCH * HDIM];
__device__ __half g_h1[BATCH * HDIM];
__device__ __half g_hall[BATCH * TBEAT * HDIM];
__device__ unsigned g_bar;

__device__ __forceinline__ float sigf(float x) { return 1.0f / (1.0f + expf(-x)); }

__device__ __forceinline__ uint32_t s2u(const void* p) {
    uint32_t a;
    asm("{ .reg .u64 t; cvta.to.shared.u64 t, %1; cvt.u32.u64 %0, t; }"
        : "=r"(a) : "l"(p));
    return a;
}

__device__ __forceinline__ void mma_f16(float* c, uint32_t a0, uint32_t a1,
                                        uint32_t a2, uint32_t a3,
                                        uint32_t b0, uint32_t b1) {
    asm volatile(
        "mma.sync.aligned.m16n8k16.row.col.f32.f16.f16.f32 "
        "{%0,%1,%2,%3}, {%4,%5,%6,%7}, {%8,%9}, {%0,%1,%2,%3};"
        : "+f"(c[0]), "+f"(c[1]), "+f"(c[2]), "+f"(c[3])
        : "r"(a0), "r"(a1), "r"(a2), "r"(a3), "r"(b0), "r"(b1));
}

__device__ __forceinline__ void ldsm4(uint32_t& r0, uint32_t& r1, uint32_t& r2,
                                      uint32_t& r3, uint32_t saddr) {
    asm volatile("ldmatrix.sync.aligned.m8n8.x4.shared.b16 {%0,%1,%2,%3}, [%4];"
                 : "=r"(r0), "=r"(r1), "=r"(r2), "=r"(r3) : "r"(saddr));
}

__device__ __forceinline__ void cpa16(uint32_t sa, const void* g) {
    asm volatile("cp.async.cg.shared.global [%0], [%1], 16;" :: "r"(sa), "l"(g));
}
#define CPA_COMMIT() asm volatile("cp.async.commit_group;")
#define CPA_WAIT(n)  asm volatile("cp.async.wait_group %0;" :: "n"(n))

// ---------------- fused prep kernel ------------------------------------------
// grid = G4 blocks x 256 threads. Converts all weights/activations to fp16,
// builds the concatenated beat weight matrix, zeroes h0 and the barrier.
__global__ void prep_all_k(const float* __restrict__ latent,
                           const float* __restrict__ inputs,
                           const float* __restrict__ mWih,
                           const float* __restrict__ mWhh,
                           const float* __restrict__ bWih,
                           const float* __restrict__ bWhh,
                           const float* __restrict__ linW) {
    const int n = blockIdx.x;
    const int tid = threadIdx.x;
    for (int k = tid; k < INDIM; k += 256)
        g_mWihH[(size_t)n * INDIM + k] = __float2half(mWih[(size_t)n * INDIM + k]);
    for (int k = tid; k < HDIM; k += 256) {
        g_mWhhH[(size_t)n * HDIM + k] = __float2half(mWhh[(size_t)n * HDIM + k]);
        g_latWH[(size_t)n * HDIM + k] = __float2half(bWih[(size_t)n * KBEAT + k]);
    }
    for (int k = tid; k < KBEAT; k += 256) {
        float v = (k < HDIM) ? bWhh[(size_t)n * HDIM + k]
                             : bWih[(size_t)n * KBEAT + k];
        g_WbH[(size_t)n * KBEAT + k] = __float2half(v);
    }
    if (n < ODIM)
        for (int k = tid; k < HDIM; k += 256)
            g_linWH[(size_t)n * HDIM + k] = __float2half(linW[(size_t)n * HDIM + k]);
    // latent: 4,194,304 / 4096 = 1024 per block
    {
        const size_t base = (size_t)n * 1024;
        for (int i = tid; i < 1024; i += 256)
            g_latentH[base + i] = __float2half(latent[base + i]);
    }
    // inputs: 16,777,216 / 4096 = 4096 per block
    {
        const size_t base = (size_t)n * 4096;
        for (int i = tid; i < 4096; i += 256)
            g_inH[base + i] = __float2half(inputs[base + i]);
    }
    // h0: 262,144 / 4096 = 64 per block
    if (tid < 64) g_h0[n * 64 + tid] = __float2half(0.f);
    if (n == 0 && tid == 0) g_bar = 0u;
}

__global__ void zero_h_k() {
    int i = blockIdx.x * blockDim.x + threadIdx.x;
    if (i < BATCH * HDIM) g_h0[i] = __float2half(0.f);
    if (i == 0) g_bar = 0u;
}

// ---------------- persistent fused LSTM recurrence ---------------------------
// Grid 64x2 = 128 CTAs (all co-resident). Weight tile (64 gate-rows x KDIM fp16)
// SMEM-resident for all NSTEPS; A streamed in 64-wide K tiles (4-stage cp.async);
// c-state in registers; adds prefetched into registers before the MMA loop;
// device-wide release/acquire barrier between steps.
template<int KDIM, bool HAS_EXTRA, int NSTEPS>
__global__ void __launch_bounds__(256, 1) lstm_persist_k(
    const __half* __restrict__ extra,
    const __half* __restrict__ W,
    const float* __restrict__ add_base,
    __half* __restrict__ hb0, __half* __restrict__ hb1,
    __half* __restrict__ tanh_out, long long tanh_rstride)
{
    constexpr int WP = KDIM + 8;
    constexpr int nk = KDIM / PBK;
    extern __shared__ __half sm[];
    const uint32_t asmb = s2u(sm);                       // 4 * BM * AP halfs
    const uint32_t wsmb = asmb + 4 * BM * AP * 2;        // resident W

    const int tid  = threadIdx.x;
    const int wid  = tid >> 5;
    const int lane = tid & 31;
    const int wm   = wid >> 1;
    const int wn   = wid & 1;
    const int q    = lane & 3;
    const int rg   = lane >> 2;
    const int nblk = blockIdx.x;
    const int mblk = blockIdx.y * BM;

    // ---- one-time: resident W tile load (gate-major smem rows) ----
    for (int idx = tid; idx < 64 * (KDIM / 8); idx += 256) {
        int sr = idx / (KDIM / 8);
        int k8 = (idx % (KDIM / 8)) * 8;
        int brow = ((sr >> 3) & 3) * HDIM + nblk * 16 + ((sr >> 5) << 3) + (sr & 7);
        cpa16(wsmb + (uint32_t)(sr * WP + k8) * 2, W + (size_t)brow * KDIM + k8);
    }
    CPA_COMMIT();
    CPA_WAIT(0);
    __syncthreads();

    // ---- A loader mapping: 1024 16B-chunks per tile, 4 per thread ----
    const int rA = tid >> 3;            // 0..31
    const int k8a = (tid & 7) << 3;     // 0..56
    uint32_t adst[4];
#pragma unroll
    for (int p = 0; p < 4; p++) adst[p] = (uint32_t)((rA + 32 * p) * AP + k8a) * 2;
    const __half* exr[4];
#pragma unroll
    for (int p = 0; p < 4; p++)
        exr[p] = HAS_EXTRA ?
            (extra + (size_t)(mblk + rA + 32 * p) * (TBEAT * ODIM) + k8a)
            : (const __half*)0;

    // ---- ldmatrix offsets ----
    const uint32_t aoff = (uint32_t)((wm * 32 + (lane & 15)) * AP + ((lane >> 4) << 3)) * 2;
    const uint32_t bbase = wsmb +
        (uint32_t)((wn * 32 + (lane & 7) + ((lane >> 4) << 3)) * WP + (((lane >> 3) & 1) << 3)) * 2;

    float creg[8];
#pragma unroll
    for (int i = 0; i < 8; i++) creg[i] = 0.f;
    unsigned barTarget = 0;

#pragma unroll 1
    for (int t = 0; t < NSTEPS; ++t) {
        const __half* hin = (t & 1) ? hb1 : hb0;
        __half* hout = (t & 1) ? hb0 : hb1;
        const int tOD = t * ODIM;

        auto issue = [&](int s, int it) {
            const int kt = it * PBK;
            const uint32_t sb = asmb + (uint32_t)s * (BM * AP * 2);
#pragma unroll
            for (int p = 0; p < 4; p++) {
                const __half* src = (HAS_EXTRA && kt >= HDIM)
                    ? (exr[p] + tOD + (kt - HDIM))
                    : (hin + (size_t)(mblk + rA + 32 * p) * HDIM + k8a + kt);
                cpa16(sb + adst[p], src);
            }
        };

        issue(0, 0); CPA_COMMIT();
        issue(1, 1); CPA_COMMIT();
        issue(2, 2); CPA_COMMIT();

        // ---- prefetch adds (independent of h) into registers ----
        float2 ads[2][2][4];                // [mt][rs][gate] -> (ps=0, ps=1)
        {
            const float* adp = add_base
                + (size_t)(HAS_EXTRA ? (t >> 4) : t) * G4;
            const int jb = nblk * 16 + wn * 8 + 2 * q;
#pragma unroll
            for (int mt = 0; mt < 2; mt++)
#pragma unroll
                for (int rs = 0; rs < 2; rs++) {
                    const int r = mblk + wm * 32 + mt * 16 + rg + rs * 8;
                    const float* ad = adp + (size_t)r * (MEAS * G4) + jb;
#pragma unroll
                    for (int gg = 0; gg < 4; gg++)
                        ads[mt][rs][gg] = *(const float2*)(ad + gg * HDIM);
                }
        }

        float acc[2][4][4];
#pragma unroll
        for (int a = 0; a < 2; a++)
#pragma unroll
            for (int b = 0; b < 4; b++)
#pragma unroll
                for (int cc = 0; cc < 4; cc++) acc[a][b][cc] = 0.f;

#pragma unroll 1
        for (int it = 0; it < nk; ++it) {
            CPA_WAIT(2);
            __syncthreads();
            const uint32_t ab = asmb + (uint32_t)(it & 3) * (BM * AP * 2);
            const uint32_t kgb = (uint32_t)(it * PBK) * 2;
#pragma unroll
            for (int ko = 0; ko < 4; ++ko) {
                uint32_t a[2][4];
#pragma unroll
                for (int mt = 0; mt < 2; mt++)
                    ldsm4(a[mt][0], a[mt][1], a[mt][2], a[mt][3],
                          ab + aoff + (uint32_t)(mt * 16 * AP + ko * 16) * 2);
                uint32_t bfr[4][2];
#pragma unroll
                for (int gp = 0; gp < 2; gp++)
                    ldsm4(bfr[gp * 2][0], bfr[gp * 2][1],
                          bfr[gp * 2 + 1][0], bfr[gp * 2 + 1][1],
                          bbase + (uint32_t)(gp * 16 * WP) * 2 + kgb + (uint32_t)(ko * 16) * 2);
#pragma unroll
                for (int nt = 0; nt < 4; nt++)
#pragma unroll
                    for (int mt = 0; mt < 2; mt++)
                        mma_f16(acc[mt][nt], a[mt][0], a[mt][1], a[mt][2], a[mt][3],
                                bfr[nt][0], bfr[nt][1]);
            }
            if (it + 3 < nk) issue((it + 3) & 3, it + 3);
            CPA_COMMIT();
        }
        CPA_WAIT(0);

        // ---- fused LSTM epilogue (c and adds in registers) ----
#pragma unroll
        for (int mt = 0; mt < 2; mt++)
#pragma unroll
            for (int rs = 0; rs < 2; rs++)
#pragma unroll
                for (int ps = 0; ps < 2; ps++) {
                    const int r = mblk + wm * 32 + mt * 16 + rg + rs * 8;
                    const int j = nblk * 16 + wn * 8 + 2 * q + ps;
                    const int ai = rs * 2 + ps;
                    float gi = acc[mt][0][ai] + (ps ? ads[mt][rs][0].y : ads[mt][rs][0].x);
                    float gf = acc[mt][1][ai] + (ps ? ads[mt][rs][1].y : ads[mt][rs][1].x);
                    float gg = acc[mt][2][ai] + (ps ? ads[mt][rs][2].y : ads[mt][rs][2].x);
                    float go = acc[mt][3][ai] + (ps ? ads[mt][rs][3].y : ads[mt][rs][3].x);
                    const int ci = mt * 4 + rs * 2 + ps;
                    float cc = sigf(gf) * creg[ci] + sigf(gi) * tanhf(gg);
                    creg[ci] = cc;
                    float hh = sigf(go) * tanhf(cc);
                    hout[r * HDIM + j] = __float2half(hh);
                    tanh_out[(size_t)r * tanh_rstride + (size_t)t * HDIM + j] =
                        __float2half(tanhf(hh));
                }

        // ---- device-wide barrier between steps ----
        if (t + 1 < NSTEPS) {
            __threadfence();
            __syncthreads();
            if (tid == 0) {
                unsigned x;
                asm volatile("atom.add.release.gpu.global.u32 %0, [%1], 1;"
                             : "=r"(x) : "l"(&g_bar));
                barTarget += GRID_CTAS;
                unsigned v;
                do {
                    asm volatile("ld.acquire.gpu.global.u32 %0, [%1];"
                                 : "=r"(v) : "l"(&g_bar));
                } while (v < barTarget);
            }
            __syncthreads();
        }
    }
}

// ---------------- fp16 tensor GEMM (non-recurrent projections) --------------
#define BK  32
#define GAP 40
#define GBP 40
#define GSTAGE_HALFS (BM * GAP + BNC * GBP)
#define GSMEM_BYTES  (4 * GSTAGE_HALFS * 2)

__global__ void __launch_bounds__(256, 2) gemm_k(
    const __half* __restrict__ A, int lda,
    const __half* __restrict__ W, int ldw, int K,
    const float* __restrict__ bias,
    float* __restrict__ C, int ldc)
{
    extern __shared__ __half sm[];
    const uint32_t smb = s2u(sm);
    const int tid  = threadIdx.x;
    const int wid  = tid >> 5;
    const int lane = tid & 31;
    const int wm   = wid >> 1;
    const int wn   = wid & 1;
    const int q    = lane & 3;
    const int rg   = lane >> 2;
    const int mblk = blockIdx.y * BM;
    const int nblk = blockIdx.x;

    const int rA0 = tid >> 2, rA1 = rA0 + 64;
    const int k8a = (tid & 3) << 3;
    const __half* Ap0 = A + (size_t)(mblk + rA0) * lda + k8a;
    const __half* Ap1 = A + (size_t)(mblk + rA1) * lda + k8a;
    const uint32_t adst0 = (uint32_t)(rA0 * GAP + k8a) * 2;
    const uint32_t adst1 = (uint32_t)(rA1 * GAP + k8a) * 2;
    const int sr  = tid >> 2;
    const int k8b = (tid & 3) << 3;
    const __half* Bp = W + (size_t)(nblk * BNC + sr) * ldw + k8b;
    const uint32_t bdst = (uint32_t)(BM * GAP + sr * GBP + k8b) * 2;

    const int nk = K / BK;
    auto issue = [&](int s, int it) {
        const int kt = it * BK;
        const uint32_t sb = smb + (uint32_t)s * (GSTAGE_HALFS * 2);
        cpa16(sb + adst0, Ap0 + kt);
        cpa16(sb + adst1, Ap1 + kt);
        cpa16(sb + bdst, Bp + kt);
    };
    issue(0, 0); CPA_COMMIT();
    issue(1, 1); CPA_COMMIT();
    issue(2, 2); CPA_COMMIT();

    const uint32_t aoff = (uint32_t)((wm * 32 + (lane & 15)) * GAP + ((lane >> 4) << 3)) * 2;
    const uint32_t boff = (uint32_t)(BM * GAP +
        (wn * 32 + (lane & 7) + ((lane >> 4) << 3)) * GBP + (((lane >> 3) & 1) << 3)) * 2;

    float acc[2][4][4];
#pragma unroll
    for (int a = 0; a < 2; a++)
#pragma unroll
        for (int b = 0; b < 4; b++)
#pragma unroll
            for (int cc = 0; cc < 4; cc++) acc[a][b][cc] = 0.f;

    int st = 0;
    for (int it = 0; it < nk; ++it) {
        CPA_WAIT(2);
        __syncthreads();
        const uint32_t sb = smb + (uint32_t)st * (GSTAGE_HALFS * 2);
#pragma unroll
        for (int ko = 0; ko < 2; ++ko) {
            uint32_t a[2][4];
#pragma unroll
            for (int mt = 0; mt < 2; mt++)
                ldsm4(a[mt][0], a[mt][1], a[mt][2], a[mt][3],
                      sb + aoff + (uint32_t)(mt * 16 * GAP + ko * 16) * 2);
            uint32_t bfr[4][2];
#pragma unroll
            for (int gp = 0; gp < 2; gp++)
                ldsm4(bfr[gp * 2][0], bfr[gp * 2][1],
                      bfr[gp * 2 + 1][0], bfr[gp * 2 + 1][1],
                      sb + boff + (uint32_t)(gp * 16 * GBP + ko * 16) * 2);
#pragma unroll
            for (int nt = 0; nt < 4; nt++)
#pragma unroll
                for (int mt = 0; mt < 2; mt++)
                    mma_f16(acc[mt][nt], a[mt][0], a[mt][1], a[mt][2], a[mt][3],
                            bfr[nt][0], bfr[nt][1]);
        }
        if (it + 3 < nk) issue((it + 3) & 3, it + 3);
        CPA_COMMIT();
        st = (st + 1) & 3;
    }
    CPA_WAIT(0);

#pragma unroll
    for (int mt = 0; mt < 2; mt++)
#pragma unroll
        for (int nt = 0; nt < 4; nt++)
#pragma unroll
            for (int rs = 0; rs < 2; rs++) {
                const int r = mblk + wm * 32 + mt * 16 + rg + rs * 8;
                const int col = nblk * BNC + wn * 32 + nt * 8 + 2 * q;
                float2 o;
                o.x = acc[mt][nt][rs * 2 + 0] + bias[col];
                o.y = acc[mt][nt][rs * 2 + 1] + bias[col + 1];
                *(float2*)&C[(size_t)r * ldc + col] = o;
            }
}

// ---------------------------------------------------------------------------
extern "C" void kernel_launch(void* const* d_in, const int* in_sizes, int n_in,
                              void* d_out, int out_size) {
    const float* latent = (const float*)d_in[0];
    const float* inputs = (const float*)d_in[1];
    const float* mWih   = (const float*)d_in[2];
    const float* mWhh   = (const float*)d_in[3];
    const float* mb     = (const float*)d_in[4];
    const float* bWih   = (const float*)d_in[5];
    const float* bWhh   = (const float*)d_in[6];
    const float* bb     = (const float*)d_in[7];
    const float* linW   = (const float*)d_in[8];
    const float* linb   = (const float*)d_in[9];
    float* out = (float*)d_out;

    __half *p_WbH, *p_mWihH, *p_mWhhH, *p_latWH, *p_linWH, *p_latentH, *p_inH;
    __half *p_lat, *p_h0, *p_h1, *p_hall;
    float *p_xg, *p_latproj;
    cudaGetSymbolAddress((void**)&p_WbH, g_WbH);
    cudaGetSymbolAddress((void**)&p_mWihH, g_mWihH);
    cudaGetSymbolAddress((void**)&p_mWhhH, g_mWhhH);
    cudaGetSymbolAddress((void**)&p_latWH, g_latWH);
    cudaGetSymbolAddress((void**)&p_linWH, g_linWH);
    cudaGetSymbolAddress((void**)&p_latentH, g_latentH);
    cudaGetSymbolAddress((void**)&p_inH, g_inH);
    cudaGetSymbolAddress((void**)&p_xg, g_xg);
    cudaGetSymbolAddress((void**)&p_lat, g_lat);
    cudaGetSymbolAddress((void**)&p_latproj, g_latproj);
    cudaGetSymbolAddress((void**)&p_h0, g_h0);
    cudaGetSymbolAddress((void**)&p_h1, g_h1);
    cudaGetSymbolAddress((void**)&p_hall, g_hall);

    const int measSmem = (4 * BM * AP + 64 * (HDIM + 8)) * 2;    // 205,824
    const int beatSmem = (4 * BM * AP + 64 * (KBEAT + 8)) * 2;   // 222,208
    cudaFuncSetAttribute(lstm_persist_k<HDIM, false, MEAS>,
                         cudaFuncAttributeMaxDynamicSharedMemorySize, measSmem);
    cudaFuncSetAttribute(lstm_persist_k<KBEAT, true, TBEAT>,
                         cudaFuncAttributeMaxDynamicSharedMemorySize, beatSmem);
    cudaFuncSetAttribute(gemm_k, cudaFuncAttributeMaxDynamicSharedMemorySize,
                         GSMEM_BYTES);

    // launch 1: fused prep (also zeroes h0 + barrier)
    prep_all_k<<<G4, 256>>>(latent, inputs, mWih, mWhh, bWih, bWhh, linW);

    // launch 2: measure input projection xg = latent @ mWih^T + mb
    gemm_k<<<dim3(G4 / BNC, (BATCH * MEAS) / BM), 256, GSMEM_BYTES>>>(
        p_latentH, INDIM, p_mWihH, INDIM, INDIM, mb, p_xg, G4);

    // launch 3: measure LSTM, persistent, 32 steps
    lstm_persist_k<HDIM, false, MEAS><<<dim3(64, 2), 256, measSmem>>>(
        nullptr, p_mWhhH, p_xg, p_h0, p_h1, p_lat, (long long)MEAS * HDIM);

    // launch 4: beat latent projection latproj = lat @ bWih[:, :H]^T + bb
    gemm_k<<<dim3(G4 / BNC, (BATCH * MEAS) / BM), 256, GSMEM_BYTES>>>(
        p_lat, HDIM, p_latWH, HDIM, HDIM, bb, p_latproj, G4);

    // launch 5: re-zero h0 + barrier
    zero_h_k<<<(BATCH * HDIM) / 256, 256>>>();

    // launch 6 (ncu -s 5 profiles this): beat LSTM, persistent, 512 steps
    lstm_persist_k<KBEAT, true, TBEAT><<<dim3(64, 2), 256, beatSmem>>>(
        p_inH, p_WbH, p_latproj, p_h0, p_h1, p_hall, (long long)TBEAT * HDIM);

    // launch 7: output head out = tanh(h_all) @ linW^T + linb
    gemm_k<<<dim3(ODIM / BNC, (BATCH * TBEAT) / BM), 256, GSMEM_BYTES>>>(
        p_hall, HDIM, p_linWH, HDIM, HDIM, linb, out, ODIM);
}

// round 9
// speedup vs baseline: 6.4814x; 1.0622x over previous
#include <cuda_runtime.h>
#include <cuda_fp16.h>
#include <math.h>
#include <stdint.h>

#define BATCH 256
#define MEAS  32
#define TBEAT 512
#define INDIM 512
#define HDIM  1024
#define ODIM  128
#define G4    4096
#define KBEAT 1152

#define BM    128
#define BNC   64
#define AP    72            // A stage pitch (halfs): 144B rows, ldmatrix conflict-free
#define PBK   64            // persistent-kernel K tile

// ---------------- scratch ----------------------------------------------------
__device__ __half g_WbH[G4 * KBEAT];    // beat weights, K order [inputs | h]
__device__ __half g_mWihH[G4 * INDIM];
__device__ __half g_mWhhH[G4 * HDIM];
__device__ __half g_latWH[G4 * HDIM];
__device__ __half g_linWH[ODIM * HDIM];
__device__ __half g_latentH[BATCH * MEAS * INDIM];
__device__ __half g_inH[BATCH * TBEAT * ODIM];
__device__ float  g_xg[BATCH * MEAS * G4];
__device__ __half g_lat[BATCH * MEAS * HDIM];
__device__ float  g_latproj[BATCH * MEAS * G4];
__device__ __half g_h0[BATCH * HDIM];
__device__ __half g_h1[BATCH * HDIM];
__device__ __half g_hall[BATCH * TBEAT * HDIM];
__device__ unsigned g_barG[64];         // [0] and [32]: per-row-group barriers

__device__ __forceinline__ float sigf(float x) { return 1.0f / (1.0f + expf(-x)); }

__device__ __forceinline__ uint32_t s2u(const void* p) {
    uint32_t a;
    asm("{ .reg .u64 t; cvta.to.shared.u64 t, %1; cvt.u32.u64 %0, t; }"
        : "=r"(a) : "l"(p));
    return a;
}

__device__ __forceinline__ void mma_f16(float* c, const uint32_t* a, const uint32_t* b) {
    asm volatile(
        "mma.sync.aligned.m16n8k16.row.col.f32.f16.f16.f32 "
        "{%0,%1,%2,%3}, {%4,%5,%6,%7}, {%8,%9}, {%0,%1,%2,%3};"
        : "+f"(c[0]), "+f"(c[1]), "+f"(c[2]), "+f"(c[3])
        : "r"(a[0]), "r"(a[1]), "r"(a[2]), "r"(a[3]), "r"(b[0]), "r"(b[1]));
}

__device__ __forceinline__ void ldsm4(uint32_t& r0, uint32_t& r1, uint32_t& r2,
                                      uint32_t& r3, uint32_t saddr) {
    asm volatile("ldmatrix.sync.aligned.m8n8.x4.shared.b16 {%0,%1,%2,%3}, [%4];"
                 : "=r"(r0), "=r"(r1), "=r"(r2), "=r"(r3) : "r"(saddr));
}

__device__ __forceinline__ void cpa16(uint32_t sa, const void* g) {
    asm volatile("cp.async.cg.shared.global [%0], [%1], 16;" :: "r"(sa), "l"(g));
}
#define CPA_COMMIT() asm volatile("cp.async.commit_group;")
#define CPA_WAIT(n)  asm volatile("cp.async.wait_group %0;" :: "n"(n))

// ---------------- fused prep kernel ------------------------------------------
__global__ void prep_all_k(const float* __restrict__ latent,
                           const float* __restrict__ inputs,
                           const float* __restrict__ mWih,
                           const float* __restrict__ mWhh,
                           const float* __restrict__ bWih,
                           const float* __restrict__ bWhh,
                           const float* __restrict__ linW) {
    const int n = blockIdx.x;
    const int tid = threadIdx.x;
    for (int k = tid; k < INDIM; k += 256)
        g_mWihH[(size_t)n * INDIM + k] = __float2half(mWih[(size_t)n * INDIM + k]);
    for (int k = tid; k < HDIM; k += 256) {
        g_mWhhH[(size_t)n * HDIM + k] = __float2half(mWhh[(size_t)n * HDIM + k]);
        g_latWH[(size_t)n * HDIM + k] = __float2half(bWih[(size_t)n * KBEAT + k]);
    }
    // beat weights, K order [inputs(128) | h(1024)]
    for (int k = tid; k < KBEAT; k += 256) {
        float v = (k < ODIM) ? bWih[(size_t)n * KBEAT + HDIM + k]
                             : bWhh[(size_t)n * HDIM + (k - ODIM)];
        g_WbH[(size_t)n * KBEAT + k] = __float2half(v);
    }
    if (n < ODIM)
        for (int k = tid; k < HDIM; k += 256)
            g_linWH[(size_t)n * HDIM + k] = __float2half(linW[(size_t)n * HDIM + k]);
    {
        const size_t base = (size_t)n * 1024;
        for (int i = tid; i < 1024; i += 256)
            g_latentH[base + i] = __float2half(latent[base + i]);
    }
    {
        const size_t base = (size_t)n * 4096;
        for (int i = tid; i < 4096; i += 256)
            g_inH[base + i] = __float2half(inputs[base + i]);
    }
    if (tid < 64) g_h0[n * 64 + tid] = __float2half(0.f);
    if (n == 0 && tid < 64) g_barG[tid] = 0u;
}

__global__ void zero_h_k() {
    int i = blockIdx.x * blockDim.x + threadIdx.x;
    if (i < BATCH * HDIM) g_h0[i] = __float2half(0.f);
    if (i < 64) g_barG[i] = 0u;
}

// ---------------- persistent fused LSTM recurrence ---------------------------
// Grid 64x2 = 128 CTAs. W tile SMEM-resident; A streamed (4 slots, 3 in flight);
// c in registers; adds + input chunks prefetched before the (split, 64-CTA)
// barrier wait; fragment double-buffering in the MMA loop.
template<int KDIM, bool HAS_EXTRA, int NSTEPS>
__global__ void __launch_bounds__(256, 1) lstm_persist_k(
    const __half* __restrict__ extra,
    const __half* __restrict__ W,
    const float* __restrict__ add_base,
    __half* __restrict__ hb0, __half* __restrict__ hb1,
    __half* __restrict__ tanh_out, long long tanh_rstride)
{
    constexpr int WP = KDIM + 8;
    constexpr int nk = KDIM / PBK;
    extern __shared__ __half sm[];
    const uint32_t asmb = s2u(sm);                       // 4 * BM * AP halfs
    const uint32_t wsmb = asmb + 4 * BM * AP * 2;        // resident W

    const int tid  = threadIdx.x;
    const int wid  = tid >> 5;
    const int lane = tid & 31;
    const int wm   = wid >> 1;
    const int wn   = wid & 1;
    const int q    = lane & 3;
    const int rg   = lane >> 2;
    const int nblk = blockIdx.x;
    const int mblk = blockIdx.y * BM;
    unsigned* barp = &g_barG[blockIdx.y * 32];

    // ---- one-time: resident W tile load (gate-major smem rows) ----
    for (int idx = tid; idx < 64 * (KDIM / 8); idx += 256) {
        int sr = idx / (KDIM / 8);
        int k8 = (idx % (KDIM / 8)) * 8;
        int brow = ((sr >> 3) & 3) * HDIM + nblk * 16 + ((sr >> 5) << 3) + (sr & 7);
        cpa16(wsmb + (uint32_t)(sr * WP + k8) * 2, W + (size_t)brow * KDIM + k8);
    }
    CPA_COMMIT();
    CPA_WAIT(0);
    __syncthreads();

    // ---- A loader mapping: 4 chunks of 16B per thread per tile ----
    const int rA = tid >> 3;
    const int k8a = (tid & 7) << 3;
    uint32_t adst[4];
#pragma unroll
    for (int p = 0; p < 4; p++) adst[p] = (uint32_t)((rA + 32 * p) * AP + k8a) * 2;
    const __half* exr[4];
#pragma unroll
    for (int p = 0; p < 4; p++)
        exr[p] = HAS_EXTRA ?
            (extra + (size_t)(mblk + rA + 32 * p) * (TBEAT * ODIM) + k8a)
            : (const __half*)0;

    // ---- ldmatrix offsets ----
    const uint32_t aoff = (uint32_t)((wm * 32 + (lane & 15)) * AP + ((lane >> 4) << 3)) * 2;
    const uint32_t bbase = wsmb +
        (uint32_t)((wn * 32 + (lane & 7) + ((lane >> 4) << 3)) * WP + (((lane >> 3) & 1) << 3)) * 2;

    float creg[8];
#pragma unroll
    for (int i = 0; i < 8; i++) creg[i] = 0.f;
    unsigned barTarget = 0;

#pragma unroll 1
    for (int t = 0; t < NSTEPS; ++t) {
        const __half* hin = (t & 1) ? hb1 : hb0;
        __half* hout = (t & 1) ? hb0 : hb1;
        const int tOD = t * ODIM;

        auto issue = [&](int it) {
            const int kt = it * PBK;
            const uint32_t sb = asmb + (uint32_t)(it & 3) * (BM * AP * 2);
#pragma unroll
            for (int p = 0; p < 4; p++) {
                const __half* src = (HAS_EXTRA && kt < ODIM)
                    ? (exr[p] + tOD + kt)
                    : (hin + (size_t)(mblk + rA + 32 * p) * HDIM + k8a
                       + (HAS_EXTRA ? (kt - ODIM) : kt));
                cpa16(sb + adst[p], src);
            }
            CPA_COMMIT();
        };

        // ---- pre-barrier: barrier-independent loads ----
        if (HAS_EXTRA) { issue(0); issue(1); }   // input chunks (K-first)

        float2 ads[2][2][4];
        {
            const float* adp = add_base
                + (size_t)(HAS_EXTRA ? (t >> 4) : t) * G4;
            const int jb = nblk * 16 + wn * 8 + 2 * q;
#pragma unroll
            for (int mt = 0; mt < 2; mt++)
#pragma unroll
                for (int rs = 0; rs < 2; rs++) {
                    const int r = mblk + wm * 32 + mt * 16 + rg + rs * 8;
                    const float* ad = adp + (size_t)r * (MEAS * G4) + jb;
#pragma unroll
                    for (int gg = 0; gg < 4; gg++)
                        ads[mt][rs][gg] = *(const float2*)(ad + gg * HDIM);
                }
        }

        // ---- split-group barrier wait (h(t-1) visibility) ----
        if (t > 0) {
            if (tid == 0) {
                unsigned v;
                do {
                    asm volatile("ld.acquire.gpu.global.u32 %0, [%1];"
                                 : "=r"(v) : "l"(barp));
                } while (v < barTarget);
            }
            __syncthreads();
        }

        // ---- post-barrier: h chunks; keep 3 groups in flight ----
        if (HAS_EXTRA) { issue(2); }
        else           { issue(0); issue(1); issue(2); }

        float acc[2][4][4];
#pragma unroll
        for (int a = 0; a < 2; a++)
#pragma unroll
            for (int b = 0; b < 4; b++)
#pragma unroll
                for (int cc = 0; cc < 4; cc++) acc[a][b][cc] = 0.f;

#pragma unroll 1
        for (int it = 0; it < nk; ++it) {
            CPA_WAIT(2);
            __syncthreads();
            const uint32_t ab = asmb + (uint32_t)(it & 3) * (BM * AP * 2);
            const uint32_t kgb = (uint32_t)(it * PBK) * 2;

            uint32_t af[2][2][4], bf[2][4][2];
            auto ldfrag = [&](int buf, int ko) {
#pragma unroll
                for (int mt = 0; mt < 2; mt++)
                    ldsm4(af[buf][mt][0], af[buf][mt][1], af[buf][mt][2], af[buf][mt][3],
                          ab + aoff + (uint32_t)(mt * 16 * AP + ko * 16) * 2);
#pragma unroll
                for (int gp = 0; gp < 2; gp++)
                    ldsm4(bf[buf][gp * 2][0], bf[buf][gp * 2][1],
                          bf[buf][gp * 2 + 1][0], bf[buf][gp * 2 + 1][1],
                          bbase + (uint32_t)(gp * 16 * WP) * 2 + kgb + (uint32_t)(ko * 16) * 2);
            };

            ldfrag(0, 0);
#pragma unroll
            for (int ko = 0; ko < 4; ++ko) {
                if (ko < 3) ldfrag((ko + 1) & 1, ko + 1);
                const int cb = ko & 1;
#pragma unroll
                for (int nt = 0; nt < 4; nt++)
#pragma unroll
                    for (int mt = 0; mt < 2; mt++)
                        mma_f16(acc[mt][nt], af[cb][mt], bf[cb][nt]);
            }
            if (it + 3 < nk) issue(it + 3);
        }
        CPA_WAIT(0);

        // ---- fused LSTM epilogue (c and adds in registers) ----
#pragma unroll
        for (int mt = 0; mt < 2; mt++)
#pragma unroll
            for (int rs = 0; rs < 2; rs++)
#pragma unroll
                for (int ps = 0; ps < 2; ps++) {
                    const int r = mblk + wm * 32 + mt * 16 + rg + rs * 8;
                    const int j = nblk * 16 + wn * 8 + 2 * q + ps;
                    const int ai = rs * 2 + ps;
                    float gi = acc[mt][0][ai] + (ps ? ads[mt][rs][0].y : ads[mt][rs][0].x);
                    float gf = acc[mt][1][ai] + (ps ? ads[mt][rs][1].y : ads[mt][rs][1].x);
                    float gg = acc[mt][2][ai] + (ps ? ads[mt][rs][2].y : ads[mt][rs][2].x);
                    float go = acc[mt][3][ai] + (ps ? ads[mt][rs][3].y : ads[mt][rs][3].x);
                    const int ci = mt * 4 + rs * 2 + ps;
                    float cc = sigf(gf) * creg[ci] + sigf(gi) * tanhf(gg);
                    creg[ci] = cc;
                    float hh = sigf(go) * tanhf(cc);
                    hout[r * HDIM + j] = __float2half(hh);
                    tanh_out[(size_t)r * tanh_rstride + (size_t)t * HDIM + j] =
                        __float2half(tanhf(hh));
                }

        // ---- release arrive (wait happens at top of next step) ----
        if (t + 1 < NSTEPS) {
            __threadfence();
            __syncthreads();
            if (tid == 0) {
                unsigned x;
                asm volatile("atom.add.release.gpu.global.u32 %0, [%1], 1;"
                             : "=r"(x) : "l"(barp));
            }
            barTarget += 64;
        }
    }
}

// ---------------- fp16 tensor GEMM (non-recurrent projections) --------------
#define BK  32
#define GAP 40
#define GBP 40
#define GSTAGE_HALFS (BM * GAP + BNC * GBP)
#define GSMEM_BYTES  (4 * GSTAGE_HALFS * 2)

__global__ void __launch_bounds__(256, 2) gemm_k(
    const __half* __restrict__ A, int lda,
    const __half* __restrict__ W, int ldw, int K,
    const float* __restrict__ bias,
    float* __restrict__ C, int ldc)
{
    extern __shared__ __half sm[];
    const uint32_t smb = s2u(sm);
    const int tid  = threadIdx.x;
    const int wid  = tid >> 5;
    const int lane = tid & 31;
    const int wm   = wid >> 1;
    const int wn   = wid & 1;
    const int q    = lane & 3;
    const int rg   = lane >> 2;
    const int mblk = blockIdx.y * BM;
    const int nblk = blockIdx.x;

    const int rA0 = tid >> 2, rA1 = rA0 + 64;
    const int k8a = (tid & 3) << 3;
    const __half* Ap0 = A + (size_t)(mblk + rA0) * lda + k8a;
    const __half* Ap1 = A + (size_t)(mblk + rA1) * lda + k8a;
    const uint32_t adst0 = (uint32_t)(rA0 * GAP + k8a) * 2;
    const uint32_t adst1 = (uint32_t)(rA1 * GAP + k8a) * 2;
    const int sr  = tid >> 2;
    const int k8b = (tid & 3) << 3;
    const __half* Bp = W + (size_t)(nblk * BNC + sr) * ldw + k8b;
    const uint32_t bdst = (uint32_t)(BM * GAP + sr * GBP + k8b) * 2;

    const int nk = K / BK;
    auto issue = [&](int s, int it) {
        const int kt = it * BK;
        const uint32_t sb = smb + (uint32_t)s * (GSTAGE_HALFS * 2);
        cpa16(sb + adst0, Ap0 + kt);
        cpa16(sb + adst1, Ap1 + kt);
        cpa16(sb + bdst, Bp + kt);
    };
    issue(0, 0); CPA_COMMIT();
    issue(1, 1); CPA_COMMIT();
    issue(2, 2); CPA_COMMIT();

    const uint32_t aoff = (uint32_t)((wm * 32 + (lane & 15)) * GAP + ((lane >> 4) << 3)) * 2;
    const uint32_t boff = (uint32_t)(BM * GAP +
        (wn * 32 + (lane & 7) + ((lane >> 4) << 3)) * GBP + (((lane >> 3) & 1) << 3)) * 2;

    float acc[2][4][4];
#pragma unroll
    for (int a = 0; a < 2; a++)
#pragma unroll
        for (int b = 0; b < 4; b++)
#pragma unroll
            for (int cc = 0; cc < 4; cc++) acc[a][b][cc] = 0.f;

    int st = 0;
    for (int it = 0; it < nk; ++it) {
        CPA_WAIT(2);
        __syncthreads();
        const uint32_t sb = smb + (uint32_t)st * (GSTAGE_HALFS * 2);
#pragma unroll
        for (int ko = 0; ko < 2; ++ko) {
            uint32_t a[2][4];
#pragma unroll
            for (int mt = 0; mt < 2; mt++)
                ldsm4(a[mt][0], a[mt][1], a[mt][2], a[mt][3],
                      sb + aoff + (uint32_t)(mt * 16 * GAP + ko * 16) * 2);
            uint32_t bfr[4][2];
#pragma unroll
            for (int gp = 0; gp < 2; gp++)
                ldsm4(bfr[gp * 2][0], bfr[gp * 2][1],
                      bfr[gp * 2 + 1][0], bfr[gp * 2 + 1][1],
                      sb + boff + (uint32_t)(gp * 16 * GBP + ko * 16) * 2);
#pragma unroll
            for (int nt = 0; nt < 4; nt++)
#pragma unroll
                for (int mt = 0; mt < 2; mt++)
                    mma_f16(acc[mt][nt], a[mt], bfr[nt]);
        }
        if (it + 3 < nk) issue((it + 3) & 3, it + 3);
        CPA_COMMIT();
        st = (st + 1) & 3;
    }
    CPA_WAIT(0);

#pragma unroll
    for (int mt = 0; mt < 2; mt++)
#pragma unroll
        for (int nt = 0; nt < 4; nt++)
#pragma unroll
            for (int rs = 0; rs < 2; rs++) {
                const int r = mblk + wm * 32 + mt * 16 + rg + rs * 8;
                const int col = nblk * BNC + wn * 32 + nt * 8 + 2 * q;
                float2 o;
                o.x = acc[mt][nt][rs * 2 + 0] + bias[col];
                o.y = acc[mt][nt][rs * 2 + 1] + bias[col + 1];
                *(float2*)&C[(size_t)r * ldc + col] = o;
            }
}

// ---------------------------------------------------------------------------
extern "C" void kernel_launch(void* const* d_in, const int* in_sizes, int n_in,
                              void* d_out, int out_size) {
    const float* latent = (const float*)d_in[0];
    const float* inputs = (const float*)d_in[1];
    const float* mWih   = (const float*)d_in[2];
    const float* mWhh   = (const float*)d_in[3];
    const float* mb     = (const float*)d_in[4];
    const float* bWih   = (const float*)d_in[5];
    const float* bWhh   = (const float*)d_in[6];
    const float* bb     = (const float*)d_in[7];
    const float* linW   = (const float*)d_in[8];
    const float* linb   = (const float*)d_in[9];
    float* out = (float*)d_out;

    __half *p_WbH, *p_mWihH, *p_mWhhH, *p_latWH, *p_linWH, *p_latentH, *p_inH;
    __half *p_lat, *p_h0, *p_h1, *p_hall;
    float *p_xg, *p_latproj;
    cudaGetSymbolAddress((void**)&p_WbH, g_WbH);
    cudaGetSymbolAddress((void**)&p_mWihH, g_mWihH);
    cudaGetSymbolAddress((void**)&p_mWhhH, g_mWhhH);
    cudaGetSymbolAddress((void**)&p_latWH, g_latWH);
    cudaGetSymbolAddress((void**)&p_linWH, g_linWH);
    cudaGetSymbolAddress((void**)&p_latentH, g_latentH);
    cudaGetSymbolAddress((void**)&p_inH, g_inH);
    cudaGetSymbolAddress((void**)&p_xg, g_xg);
    cudaGetSymbolAddress((void**)&p_lat, g_lat);
    cudaGetSymbolAddress((void**)&p_latproj, g_latproj);
    cudaGetSymbolAddress((void**)&p_h0, g_h0);
    cudaGetSymbolAddress((void**)&p_h1, g_h1);
    cudaGetSymbolAddress((void**)&p_hall, g_hall);

    const int measSmem = (4 * BM * AP + 64 * (HDIM + 8)) * 2;    // 205,824
    const int beatSmem = (4 * BM * AP + 64 * (KBEAT + 8)) * 2;   // 222,208
    cudaFuncSetAttribute(lstm_persist_k<HDIM, false, MEAS>,
                         cudaFuncAttributeMaxDynamicSharedMemorySize, measSmem);
    cudaFuncSetAttribute(lstm_persist_k<KBEAT, true, TBEAT>,
                         cudaFuncAttributeMaxDynamicSharedMemorySize, beatSmem);
    cudaFuncSetAttribute(gemm_k, cudaFuncAttributeMaxDynamicSharedMemorySize,
                         GSMEM_BYTES);

    // launch 1: fused prep (also zeroes h0 + barriers)
    prep_all_k<<<G4, 256>>>(latent, inputs, mWih, mWhh, bWih, bWhh, linW);

    // launch 2: measure input projection xg = latent @ mWih^T + mb
    gemm_k<<<dim3(G4 / BNC, (BATCH * MEAS) / BM), 256, GSMEM_BYTES>>>(
        p_latentH, INDIM, p_mWihH, INDIM, INDIM, mb, p_xg, G4);

    // launch 3: measure LSTM, persistent, 32 steps
    lstm_persist_k<HDIM, false, MEAS><<<dim3(64, 2), 256, measSmem>>>(
        nullptr, p_mWhhH, p_xg, p_h0, p_h1, p_lat, (long long)MEAS * HDIM);

    // launch 4: beat latent projection latproj = lat @ bWih[:, :H]^T + bb
    gemm_k<<<dim3(G4 / BNC, (BATCH * MEAS) / BM), 256, GSMEM_BYTES>>>(
        p_lat, HDIM, p_latWH, HDIM, HDIM, bb, p_latproj, G4);

    // launch 5: re-zero h0 + barriers
    zero_h_k<<<(BATCH * HDIM) / 256, 256>>>();

    // launch 6: beat LSTM, persistent, 512 steps
    lstm_persist_k<KBEAT, true, TBEAT><<<dim3(64, 2), 256, beatSmem>>>(
        p_inH, p_WbH, p_latproj, p_h0, p_h1, p_hall, (long long)TBEAT * HDIM);

    // launch 7: output head out = tanh(h_all) @ linW^T + linb
    gemm_k<<<dim3(ODIM / BNC, (BATCH * TBEAT) / BM), 256, GSMEM_BYTES>>>(
        p_hall, HDIM, p_linWH, HDIM, HDIM, linb, out, ODIM);
}